// round 3
// baseline (speedup 1.0000x reference)
#include <cuda_runtime.h>
#include <math.h>

#define BATCH 128
#define SEQ   32
#define IND   32
#define HID   128
#define H2    256      // 2*HID
#define NSTEP 31
#define W3C   4096     // HID*IND

// ---------------- device scratch (static, no allocation) ----------------
__device__ float gM[2][BATCH][H2][HID];   // 32 MB, double-buffered per-step M
__device__ float gZ[BATCH][HID];
__device__ float gDX[NSTEP][BATCH][IND];
__device__ float gDts[NSTEP][BATCH];

__device__ __forceinline__ float gelu_exact(float x) {
    return 0.5f * x * (1.0f + erff(x * 0.70710678118654752440f));
}

// block-wide sum for 128 threads (4 warps)
__device__ __forceinline__ float bsum128(float v, float* red) {
#pragma unroll
    for (int o = 16; o > 0; o >>= 1) v += __shfl_xor_sync(0xffffffffu, v, o);
    __syncthreads();
    if ((threadIdx.x & 31) == 0) red[threadIdx.x >> 5] = v;
    __syncthreads();
    return red[0] + red[1] + red[2] + red[3];
}

// dual block-wide sum for 256 threads (8 warps) — two values at once
__device__ __forceinline__ void bsum2(float& v0, float& v1, float red[2][8]) {
#pragma unroll
    for (int o = 16; o > 0; o >>= 1) {
        v0 += __shfl_xor_sync(0xffffffffu, v0, o);
        v1 += __shfl_xor_sync(0xffffffffu, v1, o);
    }
    __syncthreads();
    if ((threadIdx.x & 31) == 0) {
        red[0][threadIdx.x >> 5] = v0;
        red[1][threadIdx.x >> 5] = v1;
    }
    __syncthreads();
    float s0 = 0.f, s1 = 0.f;
#pragma unroll
    for (int w = 0; w < 8; w++) { s0 += red[0][w]; s1 += red[1][w]; }
    v0 = s0; v1 = s1;
}

// ---------------- init: encoder -> z0, plus dts/dX ----------------
__global__ __launch_bounds__(HID) void init_kernel(
    const float* __restrict__ path, const float* __restrict__ ts,
    const float* __restrict__ W1, const float* __restrict__ b1,
    const float* __restrict__ g1, const float* __restrict__ bt1,
    const float* __restrict__ W2, const float* __restrict__ b2,
    const float* __restrict__ g2, const float* __restrict__ bt2)
{
    int b = blockIdx.x;
    int t = threadIdx.x;  // 128 threads
    __shared__ float x0[IND];
    __shared__ float hb[HID];
    __shared__ float red[4];
    __shared__ float dtsh[NSTEP];

    if (t < IND) x0[t] = path[(size_t)(b * SEQ) * IND + t];
    __syncthreads();

    // layer 1: x0 @ enc_W1 + b1, LN, gelu
    float acc = b1[t];
#pragma unroll
    for (int i = 0; i < IND; i++) acc = fmaf(x0[i], W1[i * HID + t], acc);
    float mu  = bsum128(acc, red) * (1.0f / HID);
    float d   = acc - mu;
    float var = bsum128(d * d, red) * (1.0f / HID);
    float h0  = gelu_exact(d * rsqrtf(var + 1e-5f) * g1[t] + bt1[t]);
    hb[t] = h0;
    __syncthreads();

    // layer 2: h0 @ enc_W2 + b2, LN -> z0
    float acc2 = b2[t];
#pragma unroll 8
    for (int j = 0; j < HID; j++) acc2 = fmaf(hb[j], W2[j * HID + t], acc2);
    mu  = bsum128(acc2, red) * (1.0f / HID);
    d   = acc2 - mu;
    var = bsum128(d * d, red) * (1.0f / HID);
    gZ[b][t] = d * rsqrtf(var + 1e-5f) * g2[t] + bt2[t];

    // dts / dX
    if (t < NSTEP) {
        float dt = ts[b * SEQ + t + 1] - ts[b * SEQ + t];
        dtsh[t] = dt;
        gDts[t][b] = dt;
    }
    __syncthreads();
    for (int idx = t; idx < NSTEP * IND; idx += HID) {
        int tt = idx >> 5, i = idx & 31;
        gDX[tt][b][i] = (path[(size_t)(b * SEQ + tt + 1) * IND + i] -
                         path[(size_t)(b * SEQ + tt) * IND + i]) / dtsh[tt];
    }
}

// ---------------- fused per-step kernel: G (M precompute) + S (RK4 scan) ----------------
struct SmemS {
    float dx[2][IND];
    float hstep[2];
    float b3e[2][HID];
    float zc[2][HID];
    float za[2][HID];
    float ka[2][HID];
    float h1[2][H2];
    float h2[2][H2];
    float dpart[2][2][HID];
    float red[2][8];
};
struct SmemG { float dxs[BATCH * IND]; };
union __align__(16) StepSmem { SmemG g; SmemS s; };

__global__ __launch_bounds__(256, 2) void step_kernel(int l,
    const float* __restrict__ W3,
    const float* __restrict__ vW1, const float* __restrict__ vb1,
    const float* __restrict__ vg1, const float* __restrict__ vbt1,
    const float* __restrict__ vW2, const float* __restrict__ vb2,
    const float* __restrict__ vg2, const float* __restrict__ vbt2,
    const float* __restrict__ vb3)
{
    __shared__ StepSmem sm;
    int tid = threadIdx.x;

    if (blockIdx.x < 128) {
        // ======== G: M[l&1][b][j][h] = sum_i W3[j, h*32+i] * dX[l][b][i] ========
        if (l >= NSTEP) return;   // launch l=31 has no G work
        int jsub = tid >> 7, h = tid & 127;
        int j = blockIdx.x * 2 + jsub;

        float4 w[8];
        const float4* wr = reinterpret_cast<const float4*>(W3 + (size_t)j * W3C + h * IND);
#pragma unroll
        for (int q = 0; q < 8; q++) w[q] = wr[q];

        const float* dxg = &gDX[l][0][0];
        for (int idx = tid; idx < BATCH * IND; idx += 256) sm.g.dxs[idx] = dxg[idx];
        __syncthreads();

        float* outp = &gM[l & 1][0][j][h];
        const float4* dx4 = reinterpret_cast<const float4*>(sm.g.dxs);
        for (int b = 0; b < BATCH; b++) {
            const float4* dd = dx4 + b * 8;
            float av[4] = {0.f, 0.f, 0.f, 0.f};
#pragma unroll
            for (int q = 0; q < 8; q++) {
                float4 d = dd[q];
                av[q & 3] = fmaf(w[q].x, d.x, av[q & 3]);
                av[q & 3] = fmaf(w[q].y, d.y, av[q & 3]);
                av[q & 3] = fmaf(w[q].z, d.z, av[q & 3]);
                av[q & 3] = fmaf(w[q].w, d.w, av[q & 3]);
            }
            outp[(size_t)b * (H2 * HID)] = (av[0] + av[1]) + (av[2] + av[3]);
        }
        return;
    }

    // ======== S: RK4 scan step (l-1), two batches per block ========
    if (l == 0) return;
    int step = l - 1;
    int buf  = step & 1;
    int sb   = blockIdx.x - 128;   // 0..63
    int b0   = sb * 2;
    int bb = tid >> 7, h = tid & 127;

    if (tid < 64) {
        int bsel = tid >> 5, i = tid & 31;
        sm.s.dx[bsel][i] = gDX[step][b0 + bsel][i];
    }
    if (tid < 2) sm.s.hstep[tid] = gDts[step][b0 + tid];
    sm.s.zc[bb][h] = gZ[b0 + bb][h];
    __syncthreads();

    // b3eff[b][h] = sum_i vb3[h*32+i] * dx[b][i]; init za, ka
    {
        const float4* bp  = reinterpret_cast<const float4*>(vb3 + h * IND);
        const float4* dxp = reinterpret_cast<const float4*>(sm.s.dx[bb]);
        float a = 0.f;
#pragma unroll
        for (int q = 0; q < 8; q++) {
            float4 w4 = bp[q], d4 = dxp[q];
            a = fmaf(w4.x, d4.x, a); a = fmaf(w4.y, d4.y, a);
            a = fmaf(w4.z, d4.z, a); a = fmaf(w4.w, d4.w, a);
        }
        sm.s.b3e[bb][h] = a;
        sm.s.za[bb][h]  = sm.s.zc[bb][h];
        sm.s.ka[bb][h]  = 0.f;
    }
    __syncthreads();

    float hsA = sm.s.hstep[0], hsB = sm.s.hstep[1];

#pragma unroll 1
    for (int stage = 0; stage < 4; stage++) {
        // ---- vf layer 1: za @ vW1 + vb1, LN, gelu -> h1 ----
        {
            float s0 = 0.f, s1 = 0.f;
            const float* wp = vW1 + tid;
#pragma unroll 8
            for (int j = 0; j < HID; j++) {
                float w = wp[(size_t)j * H2];
                s0 = fmaf(sm.s.za[0][j], w, s0);
                s1 = fmaf(sm.s.za[1][j], w, s1);
            }
            s0 += vb1[tid]; s1 += vb1[tid];
            float m0 = s0, m1 = s1;
            bsum2(m0, m1, sm.s.red);
            m0 *= (1.0f / H2); m1 *= (1.0f / H2);
            float d0 = s0 - m0, d1 = s1 - m1;
            float q0 = d0 * d0, q1 = d1 * d1;
            bsum2(q0, q1, sm.s.red);
            q0 *= (1.0f / H2); q1 *= (1.0f / H2);
            float g = vg1[tid], bt = vbt1[tid];
            sm.s.h1[0][tid] = gelu_exact(d0 * rsqrtf(q0 + 1e-5f) * g + bt);
            sm.s.h1[1][tid] = gelu_exact(d1 * rsqrtf(q1 + 1e-5f) * g + bt);
        }
        __syncthreads();

        // ---- vf layer 2: h1 @ vW2 + vb2, LN, gelu -> h2 ----
        {
            float s0 = 0.f, s1 = 0.f;
            const float* wp = vW2 + tid;
#pragma unroll 8
            for (int j = 0; j < H2; j++) {
                float w = wp[(size_t)j * H2];
                s0 = fmaf(sm.s.h1[0][j], w, s0);
                s1 = fmaf(sm.s.h1[1][j], w, s1);
            }
            s0 += vb2[tid]; s1 += vb2[tid];
            float m0 = s0, m1 = s1;
            bsum2(m0, m1, sm.s.red);
            m0 *= (1.0f / H2); m1 *= (1.0f / H2);
            float d0 = s0 - m0, d1 = s1 - m1;
            float q0 = d0 * d0, q1 = d1 * d1;
            bsum2(q0, q1, sm.s.red);
            q0 *= (1.0f / H2); q1 *= (1.0f / H2);
            float g = vg2[tid], bt = vbt2[tid];
            sm.s.h2[0][tid] = gelu_exact(d0 * rsqrtf(q0 + 1e-5f) * g + bt);
            sm.s.h2[1][tid] = gelu_exact(d1 * rsqrtf(q1 + 1e-5f) * g + bt);
        }
        __syncthreads();

        // ---- drift: k = h2 @ M_b + b3eff (j split across two halves) ----
        {
            int half = tid >> 7, hh = tid & 127;
            const float* M0 = &gM[buf][b0][0][0] + hh;
            const float* M1 = M0 + (size_t)H2 * HID;
            float s0 = 0.f, s1 = 0.f;
            int j0 = half * 128;
#pragma unroll 8
            for (int j = j0; j < j0 + 128; j++) {
                s0 = fmaf(sm.s.h2[0][j], M0[(size_t)j * HID], s0);
                s1 = fmaf(sm.s.h2[1][j], M1[(size_t)j * HID], s1);
            }
            sm.s.dpart[half][0][hh] = s0;
            sm.s.dpart[half][1][hh] = s1;
        }
        __syncthreads();

        // ---- RK4 bookkeeping ----
        {
            float k  = sm.s.dpart[0][bb][h] + sm.s.dpart[1][bb][h] + sm.s.b3e[bb][h];
            float hs = bb ? hsB : hsA;
            float zc = sm.s.zc[bb][h];
            float ka = sm.s.ka[bb][h];
            if (stage == 0)      { ka = k;           sm.s.za[bb][h] = fmaf(0.5f * hs, k, zc); }
            else if (stage == 1) { ka += 2.0f * k;   sm.s.za[bb][h] = fmaf(0.5f * hs, k, zc); }
            else if (stage == 2) { ka += 2.0f * k;   sm.s.za[bb][h] = fmaf(hs, k, zc); }
            else                 { ka += k;          gZ[b0 + bb][h] = fmaf(hs * (1.0f / 6.0f), ka, zc); }
            sm.s.ka[bb][h] = ka;
        }
        __syncthreads();
    }
}

// ---------------- head + decoder (softmax over size-1 axis == identity) ----------------
__global__ __launch_bounds__(HID) void final_kernel(
    const float* __restrict__ Wv, const float* __restrict__ bv,
    const float* __restrict__ Wo, const float* __restrict__ bo,
    const float* __restrict__ dW1, const float* __restrict__ db1,
    const float* __restrict__ dW2, const float* __restrict__ db2,
    float* __restrict__ out, int out_size)
{
    int b = blockIdx.x, t = threadIdx.x;
    __shared__ float zs[HID], vs[HID], fs[HID], hD[HID];
    zs[t] = gZ[b][t];
    __syncthreads();

    float a = bv[t];
#pragma unroll 8
    for (int j = 0; j < HID; j++) a = fmaf(zs[j], Wv[j * HID + t], a);
    vs[t] = a;
    __syncthreads();

    a = bo[t];
#pragma unroll 8
    for (int j = 0; j < HID; j++) a = fmaf(vs[j], Wo[j * HID + t], a);
    fs[t] = a;
    __syncthreads();

    a = db1[t];
#pragma unroll 8
    for (int j = 0; j < HID; j++) a = fmaf(fs[j], dW1[j * HID + t], a);
    hD[t] = gelu_exact(a);
    __syncthreads();

    if (t < 10) {
        float s = db2[t];
#pragma unroll 8
        for (int j = 0; j < HID; j++) s = fmaf(hD[j], dW2[j * 10 + t], s);
        int idx = b * 10 + t;
        if (idx < out_size) out[idx] = s;
    }
    // attention_weights = softmax over a length-1 axis, mean over heads -> 1.0
    int aidx = BATCH * 10 + b;
    if (t == 0 && aidx < out_size) out[aidx] = 1.0f;
}

// ---------------- launch ----------------
extern "C" void kernel_launch(void* const* d_in, const int* in_sizes, int n_in,
                              void* d_out, int out_size)
{
    const float* path = (const float*)d_in[0];
    const float* ts   = (const float*)d_in[1];
    const float* eW1  = (const float*)d_in[2];
    const float* eb1  = (const float*)d_in[3];
    const float* eg1  = (const float*)d_in[4];
    const float* ebt1 = (const float*)d_in[5];
    const float* eW2  = (const float*)d_in[6];
    const float* eb2  = (const float*)d_in[7];
    const float* eg2  = (const float*)d_in[8];
    const float* ebt2 = (const float*)d_in[9];
    const float* vW1  = (const float*)d_in[10];
    const float* vb1  = (const float*)d_in[11];
    const float* vg1  = (const float*)d_in[12];
    const float* vbt1 = (const float*)d_in[13];
    const float* vW2  = (const float*)d_in[14];
    const float* vb2  = (const float*)d_in[15];
    const float* vg2  = (const float*)d_in[16];
    const float* vbt2 = (const float*)d_in[17];
    const float* vW3  = (const float*)d_in[18];
    const float* vb3  = (const float*)d_in[19];
    // d_in[20..23] = Wq,bq,Wk,bk  (mathematically unused: softmax over size-1 axis)
    const float* Wv   = (const float*)d_in[24];
    const float* bv   = (const float*)d_in[25];
    const float* Wo   = (const float*)d_in[26];
    const float* bo   = (const float*)d_in[27];
    const float* dW1  = (const float*)d_in[28];
    const float* db1  = (const float*)d_in[29];
    const float* dW2  = (const float*)d_in[30];
    const float* db2  = (const float*)d_in[31];

    init_kernel<<<BATCH, HID>>>(path, ts, eW1, eb1, eg1, ebt1, eW2, eb2, eg2, ebt2);

    // launch l: G-blocks compute M for step l (l<=30); S-blocks run scan step l-1 (l>=1)
    for (int l = 0; l <= NSTEP; l++) {
        step_kernel<<<192, 256>>>(l, vW3,
                                  vW1, vb1, vg1, vbt1,
                                  vW2, vb2, vg2, vbt2, vb3);
    }

    final_kernel<<<BATCH, HID>>>(Wv, bv, Wo, bo, dW1, db1, dW2, db2,
                                 (float*)d_out, out_size);
}

// round 5
// speedup vs baseline: 1.2758x; 1.2758x over previous
#include <cuda_runtime.h>
#include <math.h>

#define BATCH 128
#define SEQ   32
#define IND   32
#define HID   128
#define H2    256      // 2*HID
#define NSTEP 31
#define W3C   4096     // HID*IND
#define NBP   64       // batch pairs

typedef unsigned long long u64;

// ---------------- device scratch (static, no allocation) ----------------
// M packed by batch-pair: gM2[buf][bp][j][h] = (M[2bp][j][h], M[2bp+1][j][h])
__device__ float2 gM2[2][NBP][H2][HID];   // 32 MB double-buffered
__device__ float gZ[BATCH][HID];
__device__ float gDX[NSTEP][BATCH][IND];
__device__ float gDts[NSTEP][BATCH];

// ---------------- f32x2 packed helpers (exact fp32, 2x throughput) ------
__device__ __forceinline__ u64 fma2(u64 a, u64 b, u64 c) {
    u64 d; asm("fma.rn.f32x2 %0, %1, %2, %3;" : "=l"(d) : "l"(a), "l"(b), "l"(c)); return d;
}
__device__ __forceinline__ u64 add2(u64 a, u64 b) {
    u64 d; asm("add.rn.f32x2 %0, %1, %2;" : "=l"(d) : "l"(a), "l"(b)); return d;
}
__device__ __forceinline__ u64 pack2(float x, float y) {
    u64 r; asm("mov.b64 %0, {%1, %2};" : "=l"(r) : "f"(x), "f"(y)); return r;
}
__device__ __forceinline__ float2 unpack2(u64 v) {
    float2 r; asm("mov.b64 {%0, %1}, %2;" : "=f"(r.x), "=f"(r.y) : "l"(v)); return r;
}

__device__ __forceinline__ float gelu_exact(float x) {
    return 0.5f * x * (1.0f + erff(x * 0.70710678118654752440f));
}

// block-wide sum for 128 threads (4 warps)
__device__ __forceinline__ float bsum128(float v, float* red) {
#pragma unroll
    for (int o = 16; o > 0; o >>= 1) v += __shfl_xor_sync(0xffffffffu, v, o);
    __syncthreads();
    if ((threadIdx.x & 31) == 0) red[threadIdx.x >> 5] = v;
    __syncthreads();
    return red[0] + red[1] + red[2] + red[3];
}

// quad block-wide sum for 256 threads (8 warps), ONE barrier round
__device__ __forceinline__ void bsum4(float& a, float& b, float& c, float& d,
                                      float red[4][8]) {
#pragma unroll
    for (int o = 16; o > 0; o >>= 1) {
        a += __shfl_xor_sync(0xffffffffu, a, o);
        b += __shfl_xor_sync(0xffffffffu, b, o);
        c += __shfl_xor_sync(0xffffffffu, c, o);
        d += __shfl_xor_sync(0xffffffffu, d, o);
    }
    int w = threadIdx.x >> 5;
    if ((threadIdx.x & 31) == 0) { red[0][w] = a; red[1][w] = b; red[2][w] = c; red[3][w] = d; }
    __syncthreads();
    float A = 0.f, B = 0.f, C = 0.f, D = 0.f;
#pragma unroll
    for (int i = 0; i < 8; i++) { A += red[0][i]; B += red[1][i]; C += red[2][i]; D += red[3][i]; }
    a = A; b = B; c = C; d = D;
}

// ---------------- init: encoder -> z0, plus dts/dX ----------------
__global__ __launch_bounds__(HID) void init_kernel(
    const float* __restrict__ path, const float* __restrict__ ts,
    const float* __restrict__ W1, const float* __restrict__ b1,
    const float* __restrict__ g1, const float* __restrict__ bt1,
    const float* __restrict__ W2, const float* __restrict__ b2,
    const float* __restrict__ g2, const float* __restrict__ bt2)
{
    int b = blockIdx.x;
    int t = threadIdx.x;  // 128 threads
    __shared__ float x0[IND];
    __shared__ float hb[HID];
    __shared__ float red[4];
    __shared__ float dtsh[NSTEP];

    if (t < IND) x0[t] = path[(size_t)(b * SEQ) * IND + t];
    __syncthreads();

    float acc = b1[t];
#pragma unroll
    for (int i = 0; i < IND; i++) acc = fmaf(x0[i], W1[i * HID + t], acc);
    float mu  = bsum128(acc, red) * (1.0f / HID);
    float d   = acc - mu;
    float var = bsum128(d * d, red) * (1.0f / HID);
    float h0  = gelu_exact(d * rsqrtf(var + 1e-5f) * g1[t] + bt1[t]);
    hb[t] = h0;
    __syncthreads();

    float acc2 = b2[t];
#pragma unroll 8
    for (int j = 0; j < HID; j++) acc2 = fmaf(hb[j], W2[j * HID + t], acc2);
    mu  = bsum128(acc2, red) * (1.0f / HID);
    d   = acc2 - mu;
    var = bsum128(d * d, red) * (1.0f / HID);
    gZ[b][t] = d * rsqrtf(var + 1e-5f) * g2[t] + bt2[t];

    if (t < NSTEP) {
        float dt = ts[b * SEQ + t + 1] - ts[b * SEQ + t];
        dtsh[t] = dt;
        gDts[t][b] = dt;
    }
    __syncthreads();
    for (int idx = t; idx < NSTEP * IND; idx += HID) {
        int tt = idx >> 5, i = idx & 31;
        gDX[tt][b][i] = (path[(size_t)(b * SEQ + tt + 1) * IND + i] -
                         path[(size_t)(b * SEQ + tt) * IND + i]) / dtsh[tt];
    }
}

// ---------------- fused per-step kernel: G (M precompute) + S (RK4 scan) --
struct __align__(16) SmemG { float2 dxp[NBP][IND]; };            // 16 KB
struct __align__(16) SmemS {
    u64   zarep[2][HID];     // (za,za) replicated per batch     2 KB
    u64   h1rep[2][H2];      //                                  4 KB
    u64   h2pair[H2];        // (h2_b0, h2_b1)                   2 KB
    float p[2][2][H2];       // partials [jhalf][batch][col]     4 KB
    u64   dp2[2][HID];       // drift partials                   2 KB
    u64   zc2[HID];
    u64   ka2[HID];
    u64   b3e2[HID];         //                                  3 KB
    float red[4][8];
    float dxs[2][IND];
    float hstep[2];
};
union __align__(16) StepSmem { SmemG g; SmemS s; };

__global__ __launch_bounds__(256, 2) void step_kernel(int l,
    const float* __restrict__ W3,
    const float* __restrict__ vW1, const float* __restrict__ vb1,
    const float* __restrict__ vg1, const float* __restrict__ vbt1,
    const float* __restrict__ vW2, const float* __restrict__ vb2,
    const float* __restrict__ vg2, const float* __restrict__ vbt2,
    const float* __restrict__ vb3)
{
    __shared__ StepSmem sm;
    int tid = threadIdx.x;

    if (blockIdx.x < 128) {
        // ======== G: gM2[l&1][bp][j][h] = (sum_i W3[j][h*32+i]*dx[2bp][i],
        //                                   sum_i W3[j][h*32+i]*dx[2bp+1][i])
        if (l >= NSTEP) return;
        int jsub = tid >> 7, h = tid & 127;
        int j = blockIdx.x * 2 + jsub;

        // load + pre-replicate the 32 W3 coefficients for (j,h)
        u64 wp[32];
        {
            const float4* wr = reinterpret_cast<const float4*>(W3 + (size_t)j * W3C + h * IND);
#pragma unroll
            for (int q = 0; q < 8; q++) {
                float4 w = wr[q];
                wp[4 * q + 0] = pack2(w.x, w.x);
                wp[4 * q + 1] = pack2(w.y, w.y);
                wp[4 * q + 2] = pack2(w.z, w.z);
                wp[4 * q + 3] = pack2(w.w, w.w);
            }
        }

        // interleaved dx pairs in smem
        const float* dxg = &gDX[l][0][0];
        for (int idx = tid; idx < NBP * IND; idx += 256) {
            int bp = idx >> 5, i = idx & 31;
            sm.g.dxp[bp][i] = make_float2(dxg[(2 * bp) * IND + i],
                                          dxg[(2 * bp + 1) * IND + i]);
        }
        __syncthreads();

        float2* out = &gM2[l & 1][0][j][h];
#pragma unroll 2
        for (int bp = 0; bp < NBP; bp++) {
            const longlong2* dp = reinterpret_cast<const longlong2*>(sm.g.dxp[bp]);
            u64 a0 = 0, a1 = 0, a2 = 0, a3 = 0;
#pragma unroll
            for (int q = 0; q < 16; q++) {
                longlong2 v = dp[q];
                if ((q & 1) == 0) {
                    a0 = fma2(wp[2 * q],     (u64)v.x, a0);
                    a1 = fma2(wp[2 * q + 1], (u64)v.y, a1);
                } else {
                    a2 = fma2(wp[2 * q],     (u64)v.x, a2);
                    a3 = fma2(wp[2 * q + 1], (u64)v.y, a3);
                }
            }
            u64 s = add2(add2(a0, a1), add2(a2, a3));
            out[(size_t)bp * (H2 * HID)] = unpack2(s);
        }
        return;
    }

    // ======== S: RK4 scan step (l-1), one batch-pair per block ========
    if (l == 0) return;
    int step = l - 1;
    int buf  = step & 1;
    int bp   = blockIdx.x - 128;   // 0..63
    int b0   = bp * 2;
    int jh = tid >> 7, g = tid & 127;

    if (tid < HID) {
        int h = tid;
        float z0 = gZ[b0][h], z1 = gZ[b0 + 1][h];
        sm.s.zc2[h] = pack2(z0, z1);
        sm.s.ka2[h] = 0ull;
        sm.s.zarep[0][h] = pack2(z0, z0);
        sm.s.zarep[1][h] = pack2(z1, z1);
    } else if (tid < 192) {
        int bsel = (tid - 128) >> 5, i = tid & 31;
        sm.s.dxs[bsel][i] = gDX[step][b0 + bsel][i];
    }
    if (tid < 2) sm.s.hstep[tid] = gDts[step][b0 + tid];
    __syncthreads();

    if (tid < HID) {
        float a0 = 0.f, a1 = 0.f;
        const float* bpw = vb3 + tid * IND;
#pragma unroll
        for (int i = 0; i < IND; i++) {
            float w = bpw[i];
            a0 = fmaf(w, sm.s.dxs[0][i], a0);
            a1 = fmaf(w, sm.s.dxs[1][i], a1);
        }
        sm.s.b3e2[tid] = pack2(a0, a1);
    }
    __syncthreads();

    float hsA = sm.s.hstep[0], hsB = sm.s.hstep[1];
    u64 hs_half = pack2(0.5f * hsA, 0.5f * hsB);
    u64 hs_full = pack2(hsA, hsB);
    u64 hs_six  = pack2(hsA * (1.0f / 6.0f), hsB * (1.0f / 6.0f));
    u64 two2    = pack2(2.0f, 2.0f);

#pragma unroll 1
    for (int stage = 0; stage < 4; stage++) {
        // ---- vf layer 1 partials: cols (2g,2g+1), j-half jh ----
        {
            const u64* wrow = reinterpret_cast<const u64*>(vW1) + (size_t)(jh * 64) * (H2 / 2) + g;
            u64 acc0 = 0, acc1 = 0;
#pragma unroll 8
            for (int jj = 0; jj < 64; jj++) {
                u64 w2 = wrow[(size_t)jj * (H2 / 2)];
                int j  = jh * 64 + jj;
                acc0 = fma2(w2, sm.s.zarep[0][j], acc0);
                acc1 = fma2(w2, sm.s.zarep[1][j], acc1);
            }
            *reinterpret_cast<float2*>(&sm.s.p[jh][0][2 * g]) = unpack2(acc0);
            *reinterpret_cast<float2*>(&sm.s.p[jh][1][2 * g]) = unpack2(acc1);
        }
        __syncthreads();

        // ---- LN + gelu over 256 cols (both batches), one reduce round ----
        {
            int c = tid;
            float bias = vb1[c];
            float y0 = sm.s.p[0][0][c] + sm.s.p[1][0][c] + bias;
            float y1 = sm.s.p[0][1][c] + sm.s.p[1][1][c] + bias;
            float s0 = y0, s1 = y1, q0 = y0 * y0, q1 = y1 * y1;
            bsum4(s0, s1, q0, q1, sm.s.red);
            float mu0 = s0 * (1.0f / H2), mu1 = s1 * (1.0f / H2);
            float v0 = q0 * (1.0f / H2) - mu0 * mu0;
            float v1 = q1 * (1.0f / H2) - mu1 * mu1;
            float gg = vg1[c], bb = vbt1[c];
            float h0 = gelu_exact((y0 - mu0) * rsqrtf(v0 + 1e-5f) * gg + bb);
            float h1 = gelu_exact((y1 - mu1) * rsqrtf(v1 + 1e-5f) * gg + bb);
            sm.s.h1rep[0][c] = pack2(h0, h0);
            sm.s.h1rep[1][c] = pack2(h1, h1);
        }
        __syncthreads();

        // ---- vf layer 2 partials ----
        {
            const u64* wrow = reinterpret_cast<const u64*>(vW2) + (size_t)(jh * 128) * (H2 / 2) + g;
            u64 acc0 = 0, acc1 = 0;
#pragma unroll 8
            for (int jj = 0; jj < 128; jj++) {
                u64 w2 = wrow[(size_t)jj * (H2 / 2)];
                int j  = jh * 128 + jj;
                acc0 = fma2(w2, sm.s.h1rep[0][j], acc0);
                acc1 = fma2(w2, sm.s.h1rep[1][j], acc1);
            }
            *reinterpret_cast<float2*>(&sm.s.p[jh][0][2 * g]) = unpack2(acc0);
            *reinterpret_cast<float2*>(&sm.s.p[jh][1][2 * g]) = unpack2(acc1);
        }
        __syncthreads();

        // ---- LN + gelu -> h2pair (lanes = batches) ----
        {
            int c = tid;
            float bias = vb2[c];
            float y0 = sm.s.p[0][0][c] + sm.s.p[1][0][c] + bias;
            float y1 = sm.s.p[0][1][c] + sm.s.p[1][1][c] + bias;
            float s0 = y0, s1 = y1, q0 = y0 * y0, q1 = y1 * y1;
            bsum4(s0, s1, q0, q1, sm.s.red);
            float mu0 = s0 * (1.0f / H2), mu1 = s1 * (1.0f / H2);
            float v0 = q0 * (1.0f / H2) - mu0 * mu0;
            float v1 = q1 * (1.0f / H2) - mu1 * mu1;
            float gg = vg2[c], bb = vbt2[c];
            float h0 = gelu_exact((y0 - mu0) * rsqrtf(v0 + 1e-5f) * gg + bb);
            float h1 = gelu_exact((y1 - mu1) * rsqrtf(v1 + 1e-5f) * gg + bb);
            sm.s.h2pair[c] = pack2(h0, h1);
        }
        __syncthreads();

        // ---- drift partials: k2[h] += sum_j M2[j][h] * h2pair[j] ----
        {
            int h = g;
            const u64* mp = reinterpret_cast<const u64*>(&gM2[buf][bp][jh * 128][0]) + h;
            u64 acc = 0;
#pragma unroll 8
            for (int jj = 0; jj < 128; jj++) {
                u64 m = mp[(size_t)jj * HID];
                acc = fma2(m, sm.s.h2pair[jh * 128 + jj], acc);
            }
            sm.s.dp2[jh][h] = acc;
        }
        __syncthreads();

        // ---- packed RK4 bookkeeping ----
        if (tid < HID) {
            int h = tid;
            u64 k  = add2(add2(sm.s.dp2[0][h], sm.s.dp2[1][h]), sm.s.b3e2[h]);
            u64 zc = sm.s.zc2[h];
            u64 ka = sm.s.ka2[h];
            u64 za = 0;
            if (stage == 0)      { ka = k;                 za = fma2(hs_half, k, zc); }
            else if (stage == 1) { ka = fma2(two2, k, ka); za = fma2(hs_half, k, zc); }
            else if (stage == 2) { ka = fma2(two2, k, ka); za = fma2(hs_full, k, zc); }
            else {
                ka = add2(ka, k);
                float2 zf = unpack2(fma2(hs_six, ka, zc));
                gZ[b0][h]     = zf.x;
                gZ[b0 + 1][h] = zf.y;
            }
            sm.s.ka2[h] = ka;
            if (stage < 3) {
                float2 z = unpack2(za);
                sm.s.zarep[0][h] = pack2(z.x, z.x);
                sm.s.zarep[1][h] = pack2(z.y, z.y);
            }
        }
        __syncthreads();
    }
}

// ---------------- head + decoder (softmax over size-1 axis == identity) ----
__global__ __launch_bounds__(HID) void final_kernel(
    const float* __restrict__ Wv, const float* __restrict__ bv,
    const float* __restrict__ Wo, const float* __restrict__ bo,
    const float* __restrict__ dW1, const float* __restrict__ db1,
    const float* __restrict__ dW2, const float* __restrict__ db2,
    float* __restrict__ out, int out_size)
{
    int b = blockIdx.x, t = threadIdx.x;
    __shared__ float zs[HID], vs[HID], fs[HID], hD[HID];
    zs[t] = gZ[b][t];
    __syncthreads();

    float a = bv[t];
#pragma unroll 8
    for (int j = 0; j < HID; j++) a = fmaf(zs[j], Wv[j * HID + t], a);
    vs[t] = a;
    __syncthreads();

    a = bo[t];
#pragma unroll 8
    for (int j = 0; j < HID; j++) a = fmaf(vs[j], Wo[j * HID + t], a);
    fs[t] = a;
    __syncthreads();

    a = db1[t];
#pragma unroll 8
    for (int j = 0; j < HID; j++) a = fmaf(fs[j], dW1[j * HID + t], a);
    hD[t] = gelu_exact(a);
    __syncthreads();

    if (t < 10) {
        float s = db2[t];
#pragma unroll 8
        for (int j = 0; j < HID; j++) s = fmaf(hD[j], dW2[j * 10 + t], s);
        int idx = b * 10 + t;
        if (idx < out_size) out[idx] = s;
    }
    int aidx = BATCH * 10 + b;
    if (t == 0 && aidx < out_size) out[aidx] = 1.0f;
}

// ---------------- launch ----------------
extern "C" void kernel_launch(void* const* d_in, const int* in_sizes, int n_in,
                              void* d_out, int out_size)
{
    const float* path = (const float*)d_in[0];
    const float* ts   = (const float*)d_in[1];
    const float* eW1  = (const float*)d_in[2];
    const float* eb1  = (const float*)d_in[3];
    const float* eg1  = (const float*)d_in[4];
    const float* ebt1 = (const float*)d_in[5];
    const float* eW2  = (const float*)d_in[6];
    const float* eb2  = (const float*)d_in[7];
    const float* eg2  = (const float*)d_in[8];
    const float* ebt2 = (const float*)d_in[9];
    const float* vW1  = (const float*)d_in[10];
    const float* vb1  = (const float*)d_in[11];
    const float* vg1  = (const float*)d_in[12];
    const float* vbt1 = (const float*)d_in[13];
    const float* vW2  = (const float*)d_in[14];
    const float* vb2  = (const float*)d_in[15];
    const float* vg2  = (const float*)d_in[16];
    const float* vbt2 = (const float*)d_in[17];
    const float* vW3  = (const float*)d_in[18];
    const float* vb3  = (const float*)d_in[19];
    // d_in[20..23] = Wq,bq,Wk,bk  (mathematically unused: softmax over size-1 axis)
    const float* Wv   = (const float*)d_in[24];
    const float* bv   = (const float*)d_in[25];
    const float* Wo   = (const float*)d_in[26];
    const float* bo   = (const float*)d_in[27];
    const float* dW1  = (const float*)d_in[28];
    const float* db1  = (const float*)d_in[29];
    const float* dW2  = (const float*)d_in[30];
    const float* db2  = (const float*)d_in[31];

    init_kernel<<<BATCH, HID>>>(path, ts, eW1, eb1, eg1, ebt1, eW2, eb2, eg2, ebt2);

    // launch l: G-blocks compute M for step l (l<=30); S-blocks run scan step l-1 (l>=1)
    for (int l = 0; l <= NSTEP; l++) {
        step_kernel<<<192, 256>>>(l, vW3,
                                  vW1, vb1, vg1, vbt1,
                                  vW2, vb2, vg2, vbt2, vb3);
    }

    final_kernel<<<BATCH, HID>>>(Wv, bv, Wo, bo, dW1, db1, dW2, db2,
                                 (float*)d_out, out_size);
}

// round 8
// speedup vs baseline: 1.8102x; 1.4189x over previous
#include <cuda_runtime.h>
#include <math.h>

#define BATCH 128
#define SEQ   32
#define IND   32
#define HID   128
#define H2    256      // 2*HID
#define NSTEP 31
#define W3C   4096     // HID*IND
#define NBP   64       // batch pairs
#define GBP   32       // batch pairs per G block

typedef unsigned long long u64;

// ---------------- device scratch (static, no allocation) ----------------
// M packed by batch-pair: gM2[buf][bp][j][h] = (M[2bp][j][h], M[2bp+1][j][h])
__device__ float2 gM2[2][NBP][H2][HID];   // 32 MB double-buffered
__device__ float gZ[BATCH][HID];
__device__ float gDX[NSTEP][BATCH][IND];
__device__ float gDts[NSTEP][BATCH];

// ---------------- f32x2 packed helpers (exact fp32, 2x throughput) ------
__device__ __forceinline__ u64 fma2(u64 a, u64 b, u64 c) {
    u64 d; asm("fma.rn.f32x2 %0, %1, %2, %3;" : "=l"(d) : "l"(a), "l"(b), "l"(c)); return d;
}
__device__ __forceinline__ u64 add2(u64 a, u64 b) {
    u64 d; asm("add.rn.f32x2 %0, %1, %2;" : "=l"(d) : "l"(a), "l"(b)); return d;
}
__device__ __forceinline__ u64 pack2(float x, float y) {
    u64 r; asm("mov.b64 %0, {%1, %2};" : "=l"(r) : "f"(x), "f"(y)); return r;
}
__device__ __forceinline__ float2 unpack2(u64 v) {
    float2 r; asm("mov.b64 {%0, %1}, %2;" : "=f"(r.x), "=f"(r.y) : "l"(v)); return r;
}

__device__ __forceinline__ float gelu_exact(float x) {
    return 0.5f * x * (1.0f + erff(x * 0.70710678118654752440f));
}

// block-wide sum for 128 threads (4 warps)
__device__ __forceinline__ float bsum128(float v, float* red) {
#pragma unroll
    for (int o = 16; o > 0; o >>= 1) v += __shfl_xor_sync(0xffffffffu, v, o);
    __syncthreads();
    if ((threadIdx.x & 31) == 0) red[threadIdx.x >> 5] = v;
    __syncthreads();
    return red[0] + red[1] + red[2] + red[3];
}

// quad block-wide sum for 256 threads (8 warps), ONE barrier round
__device__ __forceinline__ void bsum4(float& a, float& b, float& c, float& d,
                                      float red[4][8]) {
#pragma unroll
    for (int o = 16; o > 0; o >>= 1) {
        a += __shfl_xor_sync(0xffffffffu, a, o);
        b += __shfl_xor_sync(0xffffffffu, b, o);
        c += __shfl_xor_sync(0xffffffffu, c, o);
        d += __shfl_xor_sync(0xffffffffu, d, o);
    }
    int w = threadIdx.x >> 5;
    if ((threadIdx.x & 31) == 0) { red[0][w] = a; red[1][w] = b; red[2][w] = c; red[3][w] = d; }
    __syncthreads();
    float A = 0.f, B = 0.f, C = 0.f, D = 0.f;
#pragma unroll
    for (int i = 0; i < 8; i++) { A += red[0][i]; B += red[1][i]; C += red[2][i]; D += red[3][i]; }
    a = A; b = B; c = C; d = D;
}

// ---------------- init: encoder -> z0, plus dts/dX ----------------
__global__ __launch_bounds__(HID) void init_kernel(
    const float* __restrict__ path, const float* __restrict__ ts,
    const float* __restrict__ W1, const float* __restrict__ b1,
    const float* __restrict__ g1, const float* __restrict__ bt1,
    const float* __restrict__ W2, const float* __restrict__ b2,
    const float* __restrict__ g2, const float* __restrict__ bt2)
{
    int b = blockIdx.x;
    int t = threadIdx.x;  // 128 threads
    __shared__ float x0[IND];
    __shared__ float hb[HID];
    __shared__ float red[4];
    __shared__ float dtsh[NSTEP];

    if (t < IND) x0[t] = path[(size_t)(b * SEQ) * IND + t];
    __syncthreads();

    float acc = b1[t];
#pragma unroll
    for (int i = 0; i < IND; i++) acc = fmaf(x0[i], W1[i * HID + t], acc);
    float mu  = bsum128(acc, red) * (1.0f / HID);
    float d   = acc - mu;
    float var = bsum128(d * d, red) * (1.0f / HID);
    float h0  = gelu_exact(d * rsqrtf(var + 1e-5f) * g1[t] + bt1[t]);
    hb[t] = h0;
    __syncthreads();

    float acc2 = b2[t];
#pragma unroll 8
    for (int j = 0; j < HID; j++) acc2 = fmaf(hb[j], W2[j * HID + t], acc2);
    mu  = bsum128(acc2, red) * (1.0f / HID);
    d   = acc2 - mu;
    var = bsum128(d * d, red) * (1.0f / HID);
    gZ[b][t] = d * rsqrtf(var + 1e-5f) * g2[t] + bt2[t];

    if (t < NSTEP) {
        float dt = ts[b * SEQ + t + 1] - ts[b * SEQ + t];
        dtsh[t] = dt;
        gDts[t][b] = dt;
    }
    __syncthreads();
    for (int idx = t; idx < NSTEP * IND; idx += HID) {
        int tt = idx >> 5, i = idx & 31;
        gDX[tt][b][i] = (path[(size_t)(b * SEQ + tt + 1) * IND + i] -
                         path[(size_t)(b * SEQ + tt) * IND + i]) / dtsh[tt];
    }
}

// ---------------- fused per-step kernel: S (RK4 scan) + G (M precompute) --
struct __align__(16) SmemG { float2 dxp[GBP][IND]; };            // 8 KB
struct __align__(16) SmemS {
    u64   zarep[2][HID];     // (za,za) replicated per batch     2 KB
    u64   h1rep[2][H2];      //                                  4 KB
    u64   h2pair[H2];        // (h2_b0, h2_b1)                   2 KB
    float p[2][2][H2];       // partials [jhalf][batch][col]     4 KB
    u64   dp2[2][HID];       // drift partials                   2 KB
    u64   zc2[HID];
    u64   ka2[HID];
    u64   b3e2[HID];         //                                  3 KB
    float red[4][8];
    float dxs[2][IND];
    float hstep[2];
};
union __align__(16) StepSmem { SmemG g; SmemS s; };

// grid = 320: blocks [0,64) = S (critical path, wave-1 placement),
//             blocks [64,320) = G (2 j-rows x 32 batch-pairs each)
__global__ __launch_bounds__(256, 2) void step_kernel(int l,
    const float* __restrict__ W3,
    const float* __restrict__ vW1, const float* __restrict__ vb1,
    const float* __restrict__ vg1, const float* __restrict__ vbt1,
    const float* __restrict__ vW2, const float* __restrict__ vb2,
    const float* __restrict__ vg2, const float* __restrict__ vbt2,
    const float* __restrict__ vb3)
{
    __shared__ StepSmem sm;
    int tid = threadIdx.x;

    if (blockIdx.x >= 64) {
        // ======== G: gM2[l&1][bp][j][h] = (sum_i W3[j][h*32+i]*dx[2bp][i],
        //                                   sum_i W3[j][h*32+i]*dx[2bp+1][i])
        if (l >= NSTEP) return;
        int gb   = blockIdx.x - 64;    // 0..255
        int jgrp = gb & 127;           // j-pair index
        int bp0  = (gb >> 7) * GBP;    // which half of the batch-pairs
        int jsub = tid >> 7, h = tid & 127;
        int j = jgrp * 2 + jsub;

        // load + pre-replicate the 32 W3 coefficients for (j,h)
        u64 wp[32];
        {
            const float4* wr = reinterpret_cast<const float4*>(W3 + (size_t)j * W3C + h * IND);
#pragma unroll
            for (int q = 0; q < 8; q++) {
                float4 w = wr[q];
                wp[4 * q + 0] = pack2(w.x, w.x);
                wp[4 * q + 1] = pack2(w.y, w.y);
                wp[4 * q + 2] = pack2(w.z, w.z);
                wp[4 * q + 3] = pack2(w.w, w.w);
            }
        }

        // interleaved dx pairs in smem for this block's 32 batch-pairs
        const float* dxg = &gDX[l][0][0];
        for (int idx = tid; idx < GBP * IND; idx += 256) {
            int bp = idx >> 5, i = idx & 31;
            sm.g.dxp[bp][i] = make_float2(dxg[(2 * (bp0 + bp)) * IND + i],
                                          dxg[(2 * (bp0 + bp) + 1) * IND + i]);
        }
        __syncthreads();

        float2* out = &gM2[l & 1][bp0][j][h];
#pragma unroll 2
        for (int bp = 0; bp < GBP; bp++) {
            const longlong2* dp = reinterpret_cast<const longlong2*>(sm.g.dxp[bp]);
            u64 a0 = 0, a1 = 0, a2 = 0, a3 = 0;
#pragma unroll
            for (int q = 0; q < 16; q++) {
                longlong2 v = dp[q];
                if ((q & 1) == 0) {
                    a0 = fma2(wp[2 * q],     (u64)v.x, a0);
                    a1 = fma2(wp[2 * q + 1], (u64)v.y, a1);
                } else {
                    a2 = fma2(wp[2 * q],     (u64)v.x, a2);
                    a3 = fma2(wp[2 * q + 1], (u64)v.y, a3);
                }
            }
            u64 s = add2(add2(a0, a1), add2(a2, a3));
            out[(size_t)bp * (H2 * HID)] = unpack2(s);
        }
        return;
    }

    // ======== S: RK4 scan step (l-1), one batch-pair per block ========
    if (l == 0) return;
    int step = l - 1;
    int buf  = step & 1;
    int bp   = blockIdx.x;         // 0..63
    int b0   = bp * 2;
    int jh = tid >> 7, g = tid & 127;

    if (tid < HID) {
        int h = tid;
        float z0 = gZ[b0][h], z1 = gZ[b0 + 1][h];
        sm.s.zc2[h] = pack2(z0, z1);
        sm.s.ka2[h] = 0ull;
        sm.s.zarep[0][h] = pack2(z0, z0);
        sm.s.zarep[1][h] = pack2(z1, z1);
    } else if (tid < 192) {
        int bsel = (tid - 128) >> 5, i = tid & 31;
        sm.s.dxs[bsel][i] = gDX[step][b0 + bsel][i];
    }
    if (tid < 2) sm.s.hstep[tid] = gDts[step][b0 + tid];
    __syncthreads();

    if (tid < HID) {
        float a0 = 0.f, a1 = 0.f;
        const float* bpw = vb3 + tid * IND;
#pragma unroll
        for (int i = 0; i < IND; i++) {
            float w = bpw[i];
            a0 = fmaf(w, sm.s.dxs[0][i], a0);
            a1 = fmaf(w, sm.s.dxs[1][i], a1);
        }
        sm.s.b3e2[tid] = pack2(a0, a1);
    }
    __syncthreads();

    float hsA = sm.s.hstep[0], hsB = sm.s.hstep[1];
    u64 hs_half = pack2(0.5f * hsA, 0.5f * hsB);
    u64 hs_full = pack2(hsA, hsB);
    u64 hs_six  = pack2(hsA * (1.0f / 6.0f), hsB * (1.0f / 6.0f));
    u64 two2    = pack2(2.0f, 2.0f);

#pragma unroll 1
    for (int stage = 0; stage < 4; stage++) {
        // ---- vf layer 1 partials: cols (2g,2g+1), j-half jh ----
        {
            const u64* wrow = reinterpret_cast<const u64*>(vW1) + (size_t)(jh * 64) * (H2 / 2) + g;
            u64 acc0 = 0, acc1 = 0;
#pragma unroll 16
            for (int jj = 0; jj < 64; jj++) {
                u64 w2 = wrow[(size_t)jj * (H2 / 2)];
                int j  = jh * 64 + jj;
                acc0 = fma2(w2, sm.s.zarep[0][j], acc0);
                acc1 = fma2(w2, sm.s.zarep[1][j], acc1);
            }
            *reinterpret_cast<float2*>(&sm.s.p[jh][0][2 * g]) = unpack2(acc0);
            *reinterpret_cast<float2*>(&sm.s.p[jh][1][2 * g]) = unpack2(acc1);
        }
        __syncthreads();

        // ---- LN + gelu over 256 cols (both batches), one reduce round ----
        {
            int c = tid;
            float bias = vb1[c];
            float y0 = sm.s.p[0][0][c] + sm.s.p[1][0][c] + bias;
            float y1 = sm.s.p[0][1][c] + sm.s.p[1][1][c] + bias;
            float s0 = y0, s1 = y1, q0 = y0 * y0, q1 = y1 * y1;
            bsum4(s0, s1, q0, q1, sm.s.red);
            float mu0 = s0 * (1.0f / H2), mu1 = s1 * (1.0f / H2);
            float v0 = q0 * (1.0f / H2) - mu0 * mu0;
            float v1 = q1 * (1.0f / H2) - mu1 * mu1;
            float gg = vg1[c], bb = vbt1[c];
            float h0 = gelu_exact((y0 - mu0) * rsqrtf(v0 + 1e-5f) * gg + bb);
            float h1 = gelu_exact((y1 - mu1) * rsqrtf(v1 + 1e-5f) * gg + bb);
            sm.s.h1rep[0][c] = pack2(h0, h0);
            sm.s.h1rep[1][c] = pack2(h1, h1);
        }
        __syncthreads();

        // ---- vf layer 2 partials ----
        {
            const u64* wrow = reinterpret_cast<const u64*>(vW2) + (size_t)(jh * 128) * (H2 / 2) + g;
            u64 acc0 = 0, acc1 = 0;
#pragma unroll 16
            for (int jj = 0; jj < 128; jj++) {
                u64 w2 = wrow[(size_t)jj * (H2 / 2)];
                int j  = jh * 128 + jj;
                acc0 = fma2(w2, sm.s.h1rep[0][j], acc0);
                acc1 = fma2(w2, sm.s.h1rep[1][j], acc1);
            }
            *reinterpret_cast<float2*>(&sm.s.p[jh][0][2 * g]) = unpack2(acc0);
            *reinterpret_cast<float2*>(&sm.s.p[jh][1][2 * g]) = unpack2(acc1);
        }
        __syncthreads();

        // ---- LN + gelu -> h2pair (lanes = batches) ----
        {
            int c = tid;
            float bias = vb2[c];
            float y0 = sm.s.p[0][0][c] + sm.s.p[1][0][c] + bias;
            float y1 = sm.s.p[0][1][c] + sm.s.p[1][1][c] + bias;
            float s0 = y0, s1 = y1, q0 = y0 * y0, q1 = y1 * y1;
            bsum4(s0, s1, q0, q1, sm.s.red);
            float mu0 = s0 * (1.0f / H2), mu1 = s1 * (1.0f / H2);
            float v0 = q0 * (1.0f / H2) - mu0 * mu0;
            float v1 = q1 * (1.0f / H2) - mu1 * mu1;
            float gg = vg2[c], bb = vbt2[c];
            float h0 = gelu_exact((y0 - mu0) * rsqrtf(v0 + 1e-5f) * gg + bb);
            float h1 = gelu_exact((y1 - mu1) * rsqrtf(v1 + 1e-5f) * gg + bb);
            sm.s.h2pair[c] = pack2(h0, h1);
        }
        __syncthreads();

        // ---- drift partials: k2[h] += sum_j M2[j][h] * h2pair[j] ----
        // dual accumulator chains + unroll 16 for MLP
        {
            int h = g;
            const u64* mp = reinterpret_cast<const u64*>(&gM2[buf][bp][jh * 128][0]) + h;
            const u64* hp = &sm.s.h2pair[jh * 128];
            u64 acc0 = 0, acc1 = 0;
#pragma unroll 16
            for (int jj = 0; jj < 128; jj += 2) {
                acc0 = fma2(mp[(size_t)jj * HID],       hp[jj],     acc0);
                acc1 = fma2(mp[(size_t)(jj + 1) * HID], hp[jj + 1], acc1);
            }
            sm.s.dp2[jh][h] = add2(acc0, acc1);
        }
        __syncthreads();

        // ---- packed RK4 bookkeeping ----
        if (tid < HID) {
            int h = tid;
            u64 k  = add2(add2(sm.s.dp2[0][h], sm.s.dp2[1][h]), sm.s.b3e2[h]);
            u64 zc = sm.s.zc2[h];
            u64 ka = sm.s.ka2[h];
            u64 za = 0;
            if (stage == 0)      { ka = k;                 za = fma2(hs_half, k, zc); }
            else if (stage == 1) { ka = fma2(two2, k, ka); za = fma2(hs_half, k, zc); }
            else if (stage == 2) { ka = fma2(two2, k, ka); za = fma2(hs_full, k, zc); }
            else {
                ka = add2(ka, k);
                float2 zf = unpack2(fma2(hs_six, ka, zc));
                gZ[b0][h]     = zf.x;
                gZ[b0 + 1][h] = zf.y;
            }
            sm.s.ka2[h] = ka;
            if (stage < 3) {
                float2 z = unpack2(za);
                sm.s.zarep[0][h] = pack2(z.x, z.x);
                sm.s.zarep[1][h] = pack2(z.y, z.y);
            }
        }
        __syncthreads();
    }
}

// ---------------- head + decoder (softmax over size-1 axis == identity) ----
__global__ __launch_bounds__(HID) void final_kernel(
    const float* __restrict__ Wv, const float* __restrict__ bv,
    const float* __restrict__ Wo, const float* __restrict__ bo,
    const float* __restrict__ dW1, const float* __restrict__ db1,
    const float* __restrict__ dW2, const float* __restrict__ db2,
    float* __restrict__ out, int out_size)
{
    int b = blockIdx.x, t = threadIdx.x;
    __shared__ float zs[HID], vs[HID], fs[HID], hD[HID];
    zs[t] = gZ[b][t];
    __syncthreads();

    float a = bv[t];
#pragma unroll 8
    for (int j = 0; j < HID; j++) a = fmaf(zs[j], Wv[j * HID + t], a);
    vs[t] = a;
    __syncthreads();

    a = bo[t];
#pragma unroll 8
    for (int j = 0; j < HID; j++) a = fmaf(vs[j], Wo[j * HID + t], a);
    fs[t] = a;
    __syncthreads();

    a = db1[t];
#pragma unroll 8
    for (int j = 0; j < HID; j++) a = fmaf(fs[j], dW1[j * HID + t], a);
    hD[t] = gelu_exact(a);
    __syncthreads();

    if (t < 10) {
        float s = db2[t];
#pragma unroll 8
        for (int j = 0; j < HID; j++) s = fmaf(hD[j], dW2[j * 10 + t], s);
        int idx = b * 10 + t;
        if (idx < out_size) out[idx] = s;
    }
    int aidx = BATCH * 10 + b;
    if (t == 0 && aidx < out_size) out[aidx] = 1.0f;
}

// ---------------- launch ----------------
extern "C" void kernel_launch(void* const* d_in, const int* in_sizes, int n_in,
                              void* d_out, int out_size)
{
    const float* path = (const float*)d_in[0];
    const float* ts   = (const float*)d_in[1];
    const float* eW1  = (const float*)d_in[2];
    const float* eb1  = (const float*)d_in[3];
    const float* eg1  = (const float*)d_in[4];
    const float* ebt1 = (const float*)d_in[5];
    const float* eW2  = (const float*)d_in[6];
    const float* eb2  = (const float*)d_in[7];
    const float* eg2  = (const float*)d_in[8];
    const float* ebt2 = (const float*)d_in[9];
    const float* vW1  = (const float*)d_in[10];
    const float* vb1  = (const float*)d_in[11];
    const float* vg1  = (const float*)d_in[12];
    const float* vbt1 = (const float*)d_in[13];
    const float* vW2  = (const float*)d_in[14];
    const float* vb2  = (const float*)d_in[15];
    const float* vg2  = (const float*)d_in[16];
    const float* vbt2 = (const float*)d_in[17];
    const float* vW3  = (const float*)d_in[18];
    const float* vb3  = (const float*)d_in[19];
    // d_in[20..23] = Wq,bq,Wk,bk  (mathematically unused: softmax over size-1 axis)
    const float* Wv   = (const float*)d_in[24];
    const float* bv   = (const float*)d_in[25];
    const float* Wo   = (const float*)d_in[26];
    const float* bo   = (const float*)d_in[27];
    const float* dW1  = (const float*)d_in[28];
    const float* db1  = (const float*)d_in[29];
    const float* dW2  = (const float*)d_in[30];
    const float* db2  = (const float*)d_in[31];

    init_kernel<<<BATCH, HID>>>(path, ts, eW1, eb1, eg1, ebt1, eW2, eb2, eg2, ebt2);

    // launch l: S-blocks run scan step l-1 (l>=1); G-blocks compute M for step l (l<=30)
    for (int l = 0; l <= NSTEP; l++) {
        step_kernel<<<320, 256>>>(l, vW3,
                                  vW1, vb1, vg1, vbt1,
                                  vW2, vb2, vg2, vbt2, vb3);
    }

    final_kernel<<<BATCH, HID>>>(Wv, bv, Wo, bo, dW1, db1, dW2, db2,
                                 (float*)d_out, out_size);
}

// round 10
// speedup vs baseline: 2.2188x; 1.2257x over previous
#include <cuda_runtime.h>
#include <cuda_fp16.h>
#include <math.h>

#define BATCH 128
#define SEQ   32
#define IND   32
#define HID   128
#define H2    256      // 2*HID
#define NSTEP 31
#define NBP   64       // batch pairs
#define NBUF  6        // M ring depth (6 x 8MB fp16 ~ 50MB, L2-resident)
#define NSB   64       // S blocks (batch pairs)
#define NGB   64       // G blocks (4 j-rows each)
#define NTHR  512

typedef unsigned long long u64;

// ---------------- device scratch (static, no allocation) ----------------
// M ring, fp16, packed by batch-pair: gMh[l%NBUF][bp][j][h] = (M_b0, M_b1)
__device__ __half2 gMh[NBUF][NBP][H2][HID];
__device__ float gZ[BATCH][HID];
__device__ float gDX[NSTEP][BATCH][IND];
__device__ float gDts[NSTEP][BATCH];
__device__ int   gDone[NSTEP];   // G blocks finished step l
__device__ int   sDone[NSTEP];   // S blocks finished consuming step l

// ---------------- helpers ------------------------------------------------
__device__ __forceinline__ u64 fma2(u64 a, u64 b, u64 c) {
    u64 d; asm("fma.rn.f32x2 %0, %1, %2, %3;" : "=l"(d) : "l"(a), "l"(b), "l"(c)); return d;
}
__device__ __forceinline__ u64 add2(u64 a, u64 b) {
    u64 d; asm("add.rn.f32x2 %0, %1, %2;" : "=l"(d) : "l"(a), "l"(b)); return d;
}
__device__ __forceinline__ u64 pack2(float x, float y) {
    u64 r; asm("mov.b64 %0, {%1, %2};" : "=l"(r) : "f"(x), "f"(y)); return r;
}
__device__ __forceinline__ float2 unpack2(u64 v) {
    float2 r; asm("mov.b64 {%0, %1}, %2;" : "=f"(r.x), "=f"(r.y) : "l"(v)); return r;
}
__device__ __forceinline__ int ld_acq(const int* p) {
    int v; asm volatile("ld.acquire.gpu.global.b32 %0, [%1];" : "=r"(v) : "l"(p)); return v;
}
// L1-bypassing load for ring-buffer M (stale-L1 safe within one launch)
__device__ __forceinline__ float2 ldcv_h2f(const __half2* p) {
    unsigned v; asm volatile("ld.global.cv.b32 %0, [%1];" : "=r"(v) : "l"(p));
    __half2 h = *reinterpret_cast<__half2*>(&v);
    return __half22float2(h);
}

__device__ __forceinline__ float gelu_exact(float x) {
    return 0.5f * x * (1.0f + erff(x * 0.70710678118654752440f));
}

// block-wide sum for 128 threads (4 warps)
__device__ __forceinline__ float bsum128(float v, float* red) {
#pragma unroll
    for (int o = 16; o > 0; o >>= 1) v += __shfl_xor_sync(0xffffffffu, v, o);
    __syncthreads();
    if ((threadIdx.x & 31) == 0) red[threadIdx.x >> 5] = v;
    __syncthreads();
    return red[0] + red[1] + red[2] + red[3];
}

// quad block-wide sum for 512 threads (16 warps), ONE barrier round
__device__ __forceinline__ void bsum4_512(float& a, float& b, float& c, float& d,
                                          float red[4][16]) {
#pragma unroll
    for (int o = 16; o > 0; o >>= 1) {
        a += __shfl_xor_sync(0xffffffffu, a, o);
        b += __shfl_xor_sync(0xffffffffu, b, o);
        c += __shfl_xor_sync(0xffffffffu, c, o);
        d += __shfl_xor_sync(0xffffffffu, d, o);
    }
    int w = threadIdx.x >> 5;
    if ((threadIdx.x & 31) == 0) { red[0][w] = a; red[1][w] = b; red[2][w] = c; red[3][w] = d; }
    __syncthreads();
    float A = 0.f, B = 0.f, C = 0.f, D = 0.f;
#pragma unroll
    for (int i = 0; i < 16; i++) { A += red[0][i]; B += red[1][i]; C += red[2][i]; D += red[3][i]; }
    a = A; b = B; c = C; d = D;
}

// ---------------- init: encoder -> z0, dts/dX, flag reset ----------------
__global__ __launch_bounds__(HID) void init_kernel(
    const float* __restrict__ path, const float* __restrict__ ts,
    const float* __restrict__ W1, const float* __restrict__ b1,
    const float* __restrict__ g1, const float* __restrict__ bt1,
    const float* __restrict__ W2, const float* __restrict__ b2,
    const float* __restrict__ g2, const float* __restrict__ bt2)
{
    int b = blockIdx.x;
    int t = threadIdx.x;  // 128 threads
    __shared__ float x0[IND];
    __shared__ float hb[HID];
    __shared__ float red[4];
    __shared__ float dtsh[NSTEP];

    if (b == 0 && t < NSTEP) { gDone[t] = 0; sDone[t] = 0; }   // reset flags every replay

    if (t < IND) x0[t] = path[(size_t)(b * SEQ) * IND + t];
    __syncthreads();

    float acc = b1[t];
#pragma unroll
    for (int i = 0; i < IND; i++) acc = fmaf(x0[i], W1[i * HID + t], acc);
    float mu  = bsum128(acc, red) * (1.0f / HID);
    float d   = acc - mu;
    float var = bsum128(d * d, red) * (1.0f / HID);
    float h0  = gelu_exact(d * rsqrtf(var + 1e-5f) * g1[t] + bt1[t]);
    hb[t] = h0;
    __syncthreads();

    float acc2 = b2[t];
#pragma unroll 8
    for (int j = 0; j < HID; j++) acc2 = fmaf(hb[j], W2[j * HID + t], acc2);
    mu  = bsum128(acc2, red) * (1.0f / HID);
    d   = acc2 - mu;
    var = bsum128(d * d, red) * (1.0f / HID);
    gZ[b][t] = d * rsqrtf(var + 1e-5f) * g2[t] + bt2[t];

    if (t < NSTEP) {
        float dt = ts[b * SEQ + t + 1] - ts[b * SEQ + t];
        dtsh[t] = dt;
        gDts[t][b] = dt;
    }
    __syncthreads();
    for (int idx = t; idx < NSTEP * IND; idx += HID) {
        int tt = idx >> 5, i = idx & 31;
        gDX[tt][b][i] = (path[(size_t)(b * SEQ + tt + 1) * IND + i] -
                         path[(size_t)(b * SEQ + tt) * IND + i]) / dtsh[tt];
    }
}

// ---------------- fused persistent kernel: 64 S blocks + 64 G blocks -----
// grid = 128 <= 148 SMs: every block is wave-1 resident => flag sync is safe.
struct __align__(16) SmemG { float2 dxp[NBP][IND]; };            // 16 KB
struct __align__(16) SmemS {
    float zc[2][HID], ka[2][HID], b3e[2][HID];
    u64   zrep[2][HID];
    u64   h1rep[2][H2];
    float h2s[2][H2];
    float p[4][2][H2];
    float red[4][16];
    float dxs[2][IND];
    float hsm[2];
    float cb1[H2], cg1[H2], cbt1[H2], cb2[H2], cg2[H2], cbt2[H2];
};
union __align__(16) FusedSmem { SmemG g; SmemS s; };

__global__ __launch_bounds__(NTHR, 1) void fused_all(
    const float* __restrict__ W3,
    const float* __restrict__ vW1, const float* __restrict__ vb1,
    const float* __restrict__ vg1, const float* __restrict__ vbt1,
    const float* __restrict__ vW2, const float* __restrict__ vb2,
    const float* __restrict__ vg2, const float* __restrict__ vbt2,
    const float* __restrict__ vb3,
    const float* __restrict__ Wv, const float* __restrict__ bv,
    const float* __restrict__ Wo, const float* __restrict__ bo,
    const float* __restrict__ dW1, const float* __restrict__ db1,
    const float* __restrict__ dW2, const float* __restrict__ db2,
    float* __restrict__ out, int out_size)
{
    __shared__ FusedSmem u;
    int tid = threadIdx.x;

    if (blockIdx.x >= NSB) {
        // ================= G: M producer, 4 j-rows per block ==============
        int gb   = blockIdx.x - NSB;     // 0..63
        int jsub = tid >> 7, h = tid & 127;
        int j = gb * 4 + jsub;

        // W3 coefficients for (j,h), replicated, register-resident for all steps
        u64 wp[32];
        {
            const float4* wr = reinterpret_cast<const float4*>(W3 + (size_t)j * (HID * IND) + h * IND);
#pragma unroll
            for (int q = 0; q < 8; q++) {
                float4 w = wr[q];
                wp[4 * q + 0] = pack2(w.x, w.x);
                wp[4 * q + 1] = pack2(w.y, w.y);
                wp[4 * q + 2] = pack2(w.z, w.z);
                wp[4 * q + 3] = pack2(w.w, w.w);
            }
        }

        for (int l = 0; l < NSTEP; l++) {
            // ring backpressure: don't overwrite a slot S hasn't drained
            if (tid == 0 && l >= NBUF) {
                while (ld_acq(&sDone[l - NBUF]) < NSB) __nanosleep(128);
            }
            __syncthreads();

            const float* dxg = &gDX[l][0][0];
            for (int idx = tid; idx < NBP * IND; idx += NTHR) {
                int bp = idx >> 5, i = idx & 31;
                u.g.dxp[bp][i] = make_float2(dxg[(2 * bp) * IND + i],
                                             dxg[(2 * bp + 1) * IND + i]);
            }
            __syncthreads();

            __half2* outp = &gMh[l % NBUF][0][j][h];
#pragma unroll 2
            for (int bp = 0; bp < NBP; bp++) {
                const longlong2* dp = reinterpret_cast<const longlong2*>(u.g.dxp[bp]);
                u64 a0 = 0, a1 = 0, a2 = 0, a3 = 0;
#pragma unroll
                for (int q = 0; q < 16; q++) {
                    longlong2 v = dp[q];
                    if ((q & 1) == 0) {
                        a0 = fma2(wp[2 * q],     (u64)v.x, a0);
                        a1 = fma2(wp[2 * q + 1], (u64)v.y, a1);
                    } else {
                        a2 = fma2(wp[2 * q],     (u64)v.x, a2);
                        a3 = fma2(wp[2 * q + 1], (u64)v.y, a3);
                    }
                }
                float2 f = unpack2(add2(add2(a0, a1), add2(a2, a3)));
                outp[(size_t)bp * (H2 * HID)] = __floats2half2_rn(f.x, f.y);
            }

            __threadfence();
            __syncthreads();
            if (tid == 0) atomicAdd(&gDone[l], 1);
        }
        return;
    }

    // ================= S: persistent RK4 scan + head/decoder =============
    int bp = blockIdx.x;
    int b0 = bp * 2;
    int jq = tid >> 7, c = tid & 127;

    if (tid < H2) {
        u.s.cb1[tid] = vb1[tid]; u.s.cg1[tid] = vg1[tid]; u.s.cbt1[tid] = vbt1[tid];
        u.s.cb2[tid] = vb2[tid]; u.s.cg2[tid] = vg2[tid]; u.s.cbt2[tid] = vbt2[tid];
    } else if (tid < H2 + HID) {
        int h = tid - H2;
        u.s.zc[0][h] = gZ[b0][h];
        u.s.zc[1][h] = gZ[b0 + 1][h];
    }
    __syncthreads();

    for (int l = 0; l < NSTEP; l++) {
        if (tid == 0) {
            while (ld_acq(&gDone[l]) < NGB) __nanosleep(64);
        }
        __syncthreads();

        if (tid < 64) { int b = tid >> 5, i = tid & 31; u.s.dxs[b][i] = gDX[l][b0 + b][i]; }
        if (tid < 2)  u.s.hsm[tid] = gDts[l][b0 + tid];
        __syncthreads();

        if (tid < 256) {
            int b = tid >> 7, h = tid & 127;
            float a = 0.f;
            const float* w = vb3 + h * IND;
#pragma unroll
            for (int i = 0; i < IND; i++) a = fmaf(w[i], u.s.dxs[b][i], a);
            u.s.b3e[b][h] = a;
            float z = u.s.zc[b][h];
            u.s.zrep[b][h] = pack2(z, z);
            u.s.ka[b][h] = 0.f;
        }
        __syncthreads();

        float hsA = u.s.hsm[0], hsB = u.s.hsm[1];
        const __half2* mbase = &gMh[l % NBUF][bp][0][0];

#pragma unroll 1
        for (int st = 0; st < 4; st++) {
            // ---- vf layer 1 partials: j-quarter jq, col pair (2c,2c+1) ----
            {
                const u64* w = reinterpret_cast<const u64*>(vW1) + (size_t)(jq * 32) * (H2 / 2) + c;
                u64 a0 = 0, a1 = 0;
#pragma unroll
                for (int jj = 0; jj < 32; jj++) {
                    u64 w2 = w[(size_t)jj * (H2 / 2)];
                    int j = jq * 32 + jj;
                    a0 = fma2(w2, u.s.zrep[0][j], a0);
                    a1 = fma2(w2, u.s.zrep[1][j], a1);
                }
                *reinterpret_cast<float2*>(&u.s.p[jq][0][2 * c]) = unpack2(a0);
                *reinterpret_cast<float2*>(&u.s.p[jq][1][2 * c]) = unpack2(a1);
            }
            __syncthreads();

            // ---- LN1 + gelu ----
            {
                float y0 = 0.f, y1 = 0.f;
                bool act = tid < H2;
                int cc = tid & (H2 - 1);
                if (act) {
                    float bias = u.s.cb1[cc];
                    y0 = u.s.p[0][0][cc] + u.s.p[1][0][cc] + u.s.p[2][0][cc] + u.s.p[3][0][cc] + bias;
                    y1 = u.s.p[0][1][cc] + u.s.p[1][1][cc] + u.s.p[2][1][cc] + u.s.p[3][1][cc] + bias;
                }
                float s0 = y0, s1 = y1, q0 = y0 * y0, q1 = y1 * y1;
                bsum4_512(s0, s1, q0, q1, u.s.red);
                if (act) {
                    float mu0 = s0 * (1.0f / H2), mu1 = s1 * (1.0f / H2);
                    float v0 = q0 * (1.0f / H2) - mu0 * mu0;
                    float v1 = q1 * (1.0f / H2) - mu1 * mu1;
                    float g = u.s.cg1[cc], bb = u.s.cbt1[cc];
                    float h0 = gelu_exact((y0 - mu0) * rsqrtf(v0 + 1e-5f) * g + bb);
                    float h1 = gelu_exact((y1 - mu1) * rsqrtf(v1 + 1e-5f) * g + bb);
                    u.s.h1rep[0][cc] = pack2(h0, h0);
                    u.s.h1rep[1][cc] = pack2(h1, h1);
                }
            }
            __syncthreads();

            // ---- vf layer 2 partials ----
            {
                const u64* w = reinterpret_cast<const u64*>(vW2) + (size_t)(jq * 64) * (H2 / 2) + c;
                u64 a0 = 0, a1 = 0;
#pragma unroll 16
                for (int jj = 0; jj < 64; jj++) {
                    u64 w2 = w[(size_t)jj * (H2 / 2)];
                    int j = jq * 64 + jj;
                    a0 = fma2(w2, u.s.h1rep[0][j], a0);
                    a1 = fma2(w2, u.s.h1rep[1][j], a1);
                }
                *reinterpret_cast<float2*>(&u.s.p[jq][0][2 * c]) = unpack2(a0);
                *reinterpret_cast<float2*>(&u.s.p[jq][1][2 * c]) = unpack2(a1);
            }
            __syncthreads();

            // ---- LN2 + gelu -> h2s ----
            {
                float y0 = 0.f, y1 = 0.f;
                bool act = tid < H2;
                int cc = tid & (H2 - 1);
                if (act) {
                    float bias = u.s.cb2[cc];
                    y0 = u.s.p[0][0][cc] + u.s.p[1][0][cc] + u.s.p[2][0][cc] + u.s.p[3][0][cc] + bias;
                    y1 = u.s.p[0][1][cc] + u.s.p[1][1][cc] + u.s.p[2][1][cc] + u.s.p[3][1][cc] + bias;
                }
                float s0 = y0, s1 = y1, q0 = y0 * y0, q1 = y1 * y1;
                bsum4_512(s0, s1, q0, q1, u.s.red);
                if (act) {
                    float mu0 = s0 * (1.0f / H2), mu1 = s1 * (1.0f / H2);
                    float v0 = q0 * (1.0f / H2) - mu0 * mu0;
                    float v1 = q1 * (1.0f / H2) - mu1 * mu1;
                    float g = u.s.cg2[cc], bb = u.s.cbt2[cc];
                    u.s.h2s[0][cc] = gelu_exact((y0 - mu0) * rsqrtf(v0 + 1e-5f) * g + bb);
                    u.s.h2s[1][cc] = gelu_exact((y1 - mu1) * rsqrtf(v1 + 1e-5f) * g + bb);
                }
            }
            __syncthreads();

            // ---- drift partials: fp16 M via L1-bypass loads ----
            {
                const __half2* mp = mbase + (size_t)(jq * 64) * HID + c;
                const float* h20 = &u.s.h2s[0][jq * 64];
                const float* h21 = &u.s.h2s[1][jq * 64];
                float k0 = 0.f, k1 = 0.f;
#pragma unroll 16
                for (int jj = 0; jj < 64; jj++) {
                    float2 m = ldcv_h2f(mp + (size_t)jj * HID);
                    k0 = fmaf(m.x, h20[jj], k0);
                    k1 = fmaf(m.y, h21[jj], k1);
                }
                u.s.p[jq][0][c] = k0;
                u.s.p[jq][1][c] = k1;
            }
            __syncthreads();

            // ---- RK4 bookkeeping ----
            if (tid < HID) {
                int h = tid;
                float k0 = u.s.p[0][0][h] + u.s.p[1][0][h] + u.s.p[2][0][h] + u.s.p[3][0][h] + u.s.b3e[0][h];
                float k1 = u.s.p[0][1][h] + u.s.p[1][1][h] + u.s.p[2][1][h] + u.s.p[3][1][h] + u.s.b3e[1][h];
                float z0 = u.s.zc[0][h], z1 = u.s.zc[1][h];
                float ka0 = u.s.ka[0][h], ka1 = u.s.ka[1][h];
                float za0 = 0.f, za1 = 0.f;
                if (st == 0) {
                    ka0 = k0; ka1 = k1;
                    za0 = fmaf(0.5f * hsA, k0, z0); za1 = fmaf(0.5f * hsB, k1, z1);
                } else if (st == 1) {
                    ka0 += 2.0f * k0; ka1 += 2.0f * k1;
                    za0 = fmaf(0.5f * hsA, k0, z0); za1 = fmaf(0.5f * hsB, k1, z1);
                } else if (st == 2) {
                    ka0 += 2.0f * k0; ka1 += 2.0f * k1;
                    za0 = fmaf(hsA, k0, z0); za1 = fmaf(hsB, k1, z1);
                } else {
                    ka0 += k0; ka1 += k1;
                    u.s.zc[0][h] = fmaf(hsA * (1.0f / 6.0f), ka0, z0);
                    u.s.zc[1][h] = fmaf(hsB * (1.0f / 6.0f), ka1, z1);
                }
                u.s.ka[0][h] = ka0; u.s.ka[1][h] = ka1;
                if (st < 3) {
                    u.s.zrep[0][h] = pack2(za0, za0);
                    u.s.zrep[1][h] = pack2(za1, za1);
                }
            }
            __syncthreads();
        }

        // release ring slot l
        if (tid == 0) { __threadfence(); atomicAdd(&sDone[l], 1); }
    }
    __syncthreads();

    // ---- head + decoder (softmax over size-1 axis == identity) ----
    {
        int bl = tid >> 7, t = tid & 127;
        if (tid < 256) {
            float a = bv[t];
#pragma unroll 8
            for (int j = 0; j < HID; j++) a = fmaf(u.s.zc[bl][j], Wv[j * HID + t], a);
            u.s.h2s[bl][t] = a;                 // vs
        }
        __syncthreads();
        if (tid < 256) {
            float a = bo[t];
#pragma unroll 8
            for (int j = 0; j < HID; j++) a = fmaf(u.s.h2s[bl][j], Wo[j * HID + t], a);
            u.s.p[0][bl][t] = a;                // final
        }
        __syncthreads();
        if (tid < 256) {
            float a = db1[t];
#pragma unroll 8
            for (int j = 0; j < HID; j++) a = fmaf(u.s.p[0][bl][j], dW1[j * HID + t], a);
            u.s.p[1][bl][t] = gelu_exact(a);    // hD
        }
        __syncthreads();
        if (tid < 256 && t < 10) {
            float s = db2[t];
#pragma unroll 8
            for (int j = 0; j < HID; j++) s = fmaf(u.s.p[1][bl][j], dW2[j * 10 + t], s);
            int idx = (b0 + bl) * 10 + t;
            if (idx < out_size) out[idx] = s;
        }
        if (tid < 2) {
            int aidx = BATCH * 10 + b0 + tid;
            if (aidx < out_size) out[aidx] = 1.0f;
        }
    }
}

// ---------------- launch: single stream, 2 graph nodes --------------------
extern "C" void kernel_launch(void* const* d_in, const int* in_sizes, int n_in,
                              void* d_out, int out_size)
{
    const float* path = (const float*)d_in[0];
    const float* ts   = (const float*)d_in[1];
    const float* eW1  = (const float*)d_in[2];
    const float* eb1  = (const float*)d_in[3];
    const float* eg1  = (const float*)d_in[4];
    const float* ebt1 = (const float*)d_in[5];
    const float* eW2  = (const float*)d_in[6];
    const float* eb2  = (const float*)d_in[7];
    const float* eg2  = (const float*)d_in[8];
    const float* ebt2 = (const float*)d_in[9];
    const float* vW1  = (const float*)d_in[10];
    const float* vb1  = (const float*)d_in[11];
    const float* vg1  = (const float*)d_in[12];
    const float* vbt1 = (const float*)d_in[13];
    const float* vW2  = (const float*)d_in[14];
    const float* vb2  = (const float*)d_in[15];
    const float* vg2  = (const float*)d_in[16];
    const float* vbt2 = (const float*)d_in[17];
    const float* vW3  = (const float*)d_in[18];
    const float* vb3  = (const float*)d_in[19];
    // d_in[20..23] = Wq,bq,Wk,bk  (mathematically unused: softmax over size-1 axis)
    const float* Wv   = (const float*)d_in[24];
    const float* bv   = (const float*)d_in[25];
    const float* Wo   = (const float*)d_in[26];
    const float* bo   = (const float*)d_in[27];
    const float* dW1  = (const float*)d_in[28];
    const float* db1  = (const float*)d_in[29];
    const float* dW2  = (const float*)d_in[30];
    const float* db2  = (const float*)d_in[31];

    init_kernel<<<BATCH, HID>>>(path, ts, eW1, eb1, eg1, ebt1, eW2, eb2, eg2, ebt2);

    fused_all<<<NSB + NGB, NTHR>>>(vW3,
                                   vW1, vb1, vg1, vbt1,
                                   vW2, vb2, vg2, vbt2, vb3,
                                   Wv, bv, Wo, bo, dW1, db1, dW2, db2,
                                   (float*)d_out, out_size);
}

// round 15
// speedup vs baseline: 2.4771x; 1.1164x over previous
#include <cuda_runtime.h>
#include <cuda_fp16.h>
#include <math.h>

#define BATCH 128
#define SEQ   32
#define IND   32
#define HID   128
#define H2    256      // 2*HID
#define NSTEP 31
#define NBP   64       // batch pairs
#define NBUF  6        // M ring depth (6 x 8MB fp16 ~ 50MB, L2-resident)
#define NSB   64       // S blocks (batch pairs)
#define NGB   64       // G blocks (4 j-rows each)
#define NTHR  512
#define DYN_SMEM (H2 * HID * 4)   // 131072 B: fp16 M tile [H2][HID] of half2

typedef unsigned long long u64;

// ---------------- device scratch (static, no allocation) ----------------
// M ring, fp16, packed by batch-pair: gMh[l%NBUF][bp][j][h] = (M_b0, M_b1)
__device__ __half2 gMh[NBUF][NBP][H2][HID];
__device__ float gZ[BATCH][HID];
__device__ float gDX[NSTEP][BATCH][IND];
__device__ float gDts[NSTEP][BATCH];
__device__ int   gDone[NSTEP];   // G blocks finished step l
__device__ int   sDone[NSTEP];   // S blocks finished consuming step l

// ---------------- helpers ------------------------------------------------
__device__ __forceinline__ u64 fma2(u64 a, u64 b, u64 c) {
    u64 d; asm("fma.rn.f32x2 %0, %1, %2, %3;" : "=l"(d) : "l"(a), "l"(b), "l"(c)); return d;
}
__device__ __forceinline__ u64 add2(u64 a, u64 b) {
    u64 d; asm("add.rn.f32x2 %0, %1, %2;" : "=l"(d) : "l"(a), "l"(b)); return d;
}
__device__ __forceinline__ u64 pack2(float x, float y) {
    u64 r; asm("mov.b64 %0, {%1, %2};" : "=l"(r) : "f"(x), "f"(y)); return r;
}
__device__ __forceinline__ float2 unpack2(u64 v) {
    float2 r; asm("mov.b64 {%0, %1}, %2;" : "=f"(r.x), "=f"(r.y) : "l"(v)); return r;
}
__device__ __forceinline__ int ld_acq(const int* p) {
    int v; asm volatile("ld.acquire.gpu.global.b32 %0, [%1];" : "=r"(v) : "l"(p)); return v;
}
__device__ __forceinline__ void red_release(int* p) {
    asm volatile("red.release.gpu.global.add.s32 [%0], %1;" :: "l"(p), "r"(1) : "memory");
}
// L2-only (coherent) vector load for ring-buffer M copy
__device__ __forceinline__ uint4 ldcg4(const uint4* p) {
    uint4 v;
    asm volatile("ld.global.cg.v4.u32 {%0,%1,%2,%3}, [%4];"
                 : "=r"(v.x), "=r"(v.y), "=r"(v.z), "=r"(v.w) : "l"(p));
    return v;
}

__device__ __forceinline__ float gelu_exact(float x) {
    return 0.5f * x * (1.0f + erff(x * 0.70710678118654752440f));
}

// block-wide sum for 128 threads (4 warps)
__device__ __forceinline__ float bsum128(float v, float* red) {
#pragma unroll
    for (int o = 16; o > 0; o >>= 1) v += __shfl_xor_sync(0xffffffffu, v, o);
    __syncthreads();
    if ((threadIdx.x & 31) == 0) red[threadIdx.x >> 5] = v;
    __syncthreads();
    return red[0] + red[1] + red[2] + red[3];
}

// quad block-wide sum for 512 threads (16 warps), ONE barrier round
__device__ __forceinline__ void bsum4_512(float& a, float& b, float& c, float& d,
                                          float red[4][16]) {
#pragma unroll
    for (int o = 16; o > 0; o >>= 1) {
        a += __shfl_xor_sync(0xffffffffu, a, o);
        b += __shfl_xor_sync(0xffffffffu, b, o);
        c += __shfl_xor_sync(0xffffffffu, c, o);
        d += __shfl_xor_sync(0xffffffffu, d, o);
    }
    int w = threadIdx.x >> 5;
    if ((threadIdx.x & 31) == 0) { red[0][w] = a; red[1][w] = b; red[2][w] = c; red[3][w] = d; }
    __syncthreads();
    float A = 0.f, B = 0.f, C = 0.f, D = 0.f;
#pragma unroll
    for (int i = 0; i < 16; i++) { A += red[0][i]; B += red[1][i]; C += red[2][i]; D += red[3][i]; }
    a = A; b = B; c = C; d = D;
}

// ---------------- init: encoder -> z0, dts/dX, flag reset ----------------
__global__ __launch_bounds__(HID) void init_kernel(
    const float* __restrict__ path, const float* __restrict__ ts,
    const float* __restrict__ W1, const float* __restrict__ b1,
    const float* __restrict__ g1, const float* __restrict__ bt1,
    const float* __restrict__ W2, const float* __restrict__ b2,
    const float* __restrict__ g2, const float* __restrict__ bt2)
{
    int b = blockIdx.x;
    int t = threadIdx.x;  // 128 threads
    __shared__ float x0[IND];
    __shared__ float hb[HID];
    __shared__ float red[4];
    __shared__ float dtsh[NSTEP];

    if (b == 0 && t < NSTEP) { gDone[t] = 0; sDone[t] = 0; }   // reset flags every replay

    if (t < IND) x0[t] = path[(size_t)(b * SEQ) * IND + t];
    __syncthreads();

    float acc = b1[t];
#pragma unroll
    for (int i = 0; i < IND; i++) acc = fmaf(x0[i], W1[i * HID + t], acc);
    float mu  = bsum128(acc, red) * (1.0f / HID);
    float d   = acc - mu;
    float var = bsum128(d * d, red) * (1.0f / HID);
    float h0  = gelu_exact(d * rsqrtf(var + 1e-5f) * g1[t] + bt1[t]);
    hb[t] = h0;
    __syncthreads();

    float acc2 = b2[t];
#pragma unroll 8
    for (int j = 0; j < HID; j++) acc2 = fmaf(hb[j], W2[j * HID + t], acc2);
    mu  = bsum128(acc2, red) * (1.0f / HID);
    d   = acc2 - mu;
    var = bsum128(d * d, red) * (1.0f / HID);
    gZ[b][t] = d * rsqrtf(var + 1e-5f) * g2[t] + bt2[t];

    if (t < NSTEP) {
        float dt = ts[b * SEQ + t + 1] - ts[b * SEQ + t];
        dtsh[t] = dt;
        gDts[t][b] = dt;
    }
    __syncthreads();
    for (int idx = t; idx < NSTEP * IND; idx += HID) {
        int tt = idx >> 5, i = idx & 31;
        gDX[tt][b][i] = (path[(size_t)(b * SEQ + tt + 1) * IND + i] -
                         path[(size_t)(b * SEQ + tt) * IND + i]) / dtsh[tt];
    }
}

// ---------------- fused persistent kernel: 64 S blocks + 64 G blocks -----
// grid = 128 <= 148 SMs: every block is wave-1 resident => flag sync is safe.
struct __align__(16) SmemG { float2 dxp[NBP][IND]; };            // 16 KB
struct __align__(16) SmemS {
    u64   zrep[2][HID];      // (za,za) replicated per batch     2 KB
    u64   h1rep[2][H2];      //                                  4 KB
    u64   h2pair[H2];        // (h2_b0, h2_b1)                   2 KB
    float p[4][2][H2];       // layer partials + head scratch    8 KB
    u64   dp2[4][HID];       // drift partials                   4 KB
    u64   zc2[HID], ka2[HID], b3e2[HID];                       // 3 KB
    float red[4][16];
    float dxs[2][IND];
    float hsm[2];
    float cb1[H2], cg1[H2], cbt1[H2], cb2[H2], cg2[H2], cbt2[H2]; // 6 KB
};
union __align__(16) FusedSmem { SmemG g; SmemS s; };

__global__ __launch_bounds__(NTHR, 1) void fused_all(
    const float* __restrict__ W3,
    const float* __restrict__ vW1, const float* __restrict__ vb1,
    const float* __restrict__ vg1, const float* __restrict__ vbt1,
    const float* __restrict__ vW2, const float* __restrict__ vb2,
    const float* __restrict__ vg2, const float* __restrict__ vbt2,
    const float* __restrict__ vb3,
    const float* __restrict__ Wv, const float* __restrict__ bv,
    const float* __restrict__ Wo, const float* __restrict__ bo,
    const float* __restrict__ dW1, const float* __restrict__ db1,
    const float* __restrict__ dW2, const float* __restrict__ db2,
    float* __restrict__ out, int out_size)
{
    extern __shared__ __align__(16) unsigned char dynsm[];
    __half2* sM = reinterpret_cast<__half2*>(dynsm);   // [H2][HID] M tile (S only)
    __shared__ FusedSmem u;
    int tid = threadIdx.x;

    if (blockIdx.x >= NSB) {
        // ================= G: M producer, 4 j-rows per block ==============
        int gb   = blockIdx.x - NSB;     // 0..63
        int jsub = tid >> 7, h = tid & 127;
        int j = gb * 4 + jsub;

        // W3 coefficients for (j,h), replicated, register-resident for all steps
        u64 wp[32];
        {
            const float4* wr = reinterpret_cast<const float4*>(W3 + (size_t)j * (HID * IND) + h * IND);
#pragma unroll
            for (int q = 0; q < 8; q++) {
                float4 w = wr[q];
                wp[4 * q + 0] = pack2(w.x, w.x);
                wp[4 * q + 1] = pack2(w.y, w.y);
                wp[4 * q + 2] = pack2(w.z, w.z);
                wp[4 * q + 3] = pack2(w.w, w.w);
            }
        }

        for (int l = 0; l < NSTEP; l++) {
            // ring backpressure: don't overwrite a slot S hasn't drained
            if (tid == 0 && l >= NBUF) {
                while (ld_acq(&sDone[l - NBUF]) < NSB) __nanosleep(128);
            }
            __syncthreads();

            const float* dxg = &gDX[l][0][0];
            for (int idx = tid; idx < NBP * IND; idx += NTHR) {
                int bp = idx >> 5, i = idx & 31;
                u.g.dxp[bp][i] = make_float2(dxg[(2 * bp) * IND + i],
                                             dxg[(2 * bp + 1) * IND + i]);
            }
            __syncthreads();

            __half2* outp = &gMh[l % NBUF][0][j][h];
#pragma unroll 2
            for (int bp = 0; bp < NBP; bp++) {
                const longlong2* dp = reinterpret_cast<const longlong2*>(u.g.dxp[bp]);
                u64 a0 = 0, a1 = 0, a2 = 0, a3 = 0;
#pragma unroll
                for (int q = 0; q < 16; q++) {
                    longlong2 v = dp[q];
                    if ((q & 1) == 0) {
                        a0 = fma2(wp[2 * q],     (u64)v.x, a0);
                        a1 = fma2(wp[2 * q + 1], (u64)v.y, a1);
                    } else {
                        a2 = fma2(wp[2 * q],     (u64)v.x, a2);
                        a3 = fma2(wp[2 * q + 1], (u64)v.y, a3);
                    }
                }
                float2 f = unpack2(add2(add2(a0, a1), add2(a2, a3)));
                outp[(size_t)bp * (H2 * HID)] = __floats2half2_rn(f.x, f.y);
            }

            // one-thread release after barrier (replaces 256 MEMBARs)
            __syncthreads();
            if (tid == 0) red_release(&gDone[l]);
        }
        return;
    }

    // ================= S: persistent RK4 scan + head/decoder =============
    int bp = blockIdx.x;
    int b0 = bp * 2;
    int jq = tid >> 7, c = tid & 127;

    if (tid < H2) {
        u.s.cb1[tid] = vb1[tid]; u.s.cg1[tid] = vg1[tid]; u.s.cbt1[tid] = vbt1[tid];
        u.s.cb2[tid] = vb2[tid]; u.s.cg2[tid] = vg2[tid]; u.s.cbt2[tid] = vbt2[tid];
    } else if (tid < H2 + HID) {
        int h = tid - H2;
        u.s.zc2[h] = pack2(gZ[b0][h], gZ[b0 + 1][h]);
    }
    __syncthreads();

    for (int l = 0; l < NSTEP; l++) {
        if (tid == 0) {
            while (ld_acq(&gDone[l]) < NGB) __nanosleep(64);
        }
        __syncthreads();

        // ---- stage M tile into smem: 128 KB coherent .cg copy ----
        {
            const uint4* src = reinterpret_cast<const uint4*>(&gMh[l % NBUF][bp][0][0]);
            uint4* dst = reinterpret_cast<uint4*>(sM);
#pragma unroll
            for (int it = 0; it < 16; it++) {
                int idx = it * NTHR + tid;
                dst[idx] = ldcg4(src + idx);
            }
        }
        if (tid < 64) { int b = tid >> 5, i = tid & 31; u.s.dxs[b][i] = gDX[l][b0 + b][i]; }
        if (tid < 2)  u.s.hsm[tid] = gDts[l][b0 + tid];
        __syncthreads();

        if (tid < HID) {
            float a0 = 0.f, a1 = 0.f;
            const float* w = vb3 + tid * IND;
#pragma unroll
            for (int i = 0; i < IND; i++) {
                a0 = fmaf(w[i], u.s.dxs[0][i], a0);
                a1 = fmaf(w[i], u.s.dxs[1][i], a1);
            }
            u.s.b3e2[tid] = pack2(a0, a1);
            float2 z = unpack2(u.s.zc2[tid]);
            u.s.zrep[0][tid] = pack2(z.x, z.x);
            u.s.zrep[1][tid] = pack2(z.y, z.y);
            u.s.ka2[tid] = 0ull;
        }
        __syncthreads();

        float hsA = u.s.hsm[0], hsB = u.s.hsm[1];
        u64 hs_half = pack2(0.5f * hsA, 0.5f * hsB);
        u64 hs_full = pack2(hsA, hsB);
        u64 hs_six  = pack2(hsA * (1.0f / 6.0f), hsB * (1.0f / 6.0f));
        u64 two2    = pack2(2.0f, 2.0f);

#pragma unroll 1
        for (int st = 0; st < 4; st++) {
            // ---- vf layer 1 partials: j-quarter jq, col pair (2c,2c+1) ----
            {
                const u64* w = reinterpret_cast<const u64*>(vW1) + (size_t)(jq * 32) * (H2 / 2) + c;
                u64 a0 = 0, a1 = 0;
#pragma unroll
                for (int jj = 0; jj < 32; jj++) {
                    u64 w2 = w[(size_t)jj * (H2 / 2)];
                    int j = jq * 32 + jj;
                    a0 = fma2(w2, u.s.zrep[0][j], a0);
                    a1 = fma2(w2, u.s.zrep[1][j], a1);
                }
                *reinterpret_cast<float2*>(&u.s.p[jq][0][2 * c]) = unpack2(a0);
                *reinterpret_cast<float2*>(&u.s.p[jq][1][2 * c]) = unpack2(a1);
            }
            __syncthreads();

            // ---- LN1 + gelu ----
            {
                float y0 = 0.f, y1 = 0.f;
                bool act = tid < H2;
                int cc = tid & (H2 - 1);
                if (act) {
                    float bias = u.s.cb1[cc];
                    y0 = u.s.p[0][0][cc] + u.s.p[1][0][cc] + u.s.p[2][0][cc] + u.s.p[3][0][cc] + bias;
                    y1 = u.s.p[0][1][cc] + u.s.p[1][1][cc] + u.s.p[2][1][cc] + u.s.p[3][1][cc] + bias;
                }
                float s0 = y0, s1 = y1, q0 = y0 * y0, q1 = y1 * y1;
                bsum4_512(s0, s1, q0, q1, u.s.red);
                if (act) {
                    float mu0 = s0 * (1.0f / H2), mu1 = s1 * (1.0f / H2);
                    float v0 = q0 * (1.0f / H2) - mu0 * mu0;
                    float v1 = q1 * (1.0f / H2) - mu1 * mu1;
                    float g = u.s.cg1[cc], bb = u.s.cbt1[cc];
                    float h0 = gelu_exact((y0 - mu0) * rsqrtf(v0 + 1e-5f) * g + bb);
                    float h1 = gelu_exact((y1 - mu1) * rsqrtf(v1 + 1e-5f) * g + bb);
                    u.s.h1rep[0][cc] = pack2(h0, h0);
                    u.s.h1rep[1][cc] = pack2(h1, h1);
                }
            }
            __syncthreads();

            // ---- vf layer 2 partials ----
            {
                const u64* w = reinterpret_cast<const u64*>(vW2) + (size_t)(jq * 64) * (H2 / 2) + c;
                u64 a0 = 0, a1 = 0;
#pragma unroll 16
                for (int jj = 0; jj < 64; jj++) {
                    u64 w2 = w[(size_t)jj * (H2 / 2)];
                    int j = jq * 64 + jj;
                    a0 = fma2(w2, u.s.h1rep[0][j], a0);
                    a1 = fma2(w2, u.s.h1rep[1][j], a1);
                }
                *reinterpret_cast<float2*>(&u.s.p[jq][0][2 * c]) = unpack2(a0);
                *reinterpret_cast<float2*>(&u.s.p[jq][1][2 * c]) = unpack2(a1);
            }
            __syncthreads();

            // ---- LN2 + gelu -> h2pair (lanes = batches) ----
            {
                float y0 = 0.f, y1 = 0.f;
                bool act = tid < H2;
                int cc = tid & (H2 - 1);
                if (act) {
                    float bias = u.s.cb2[cc];
                    y0 = u.s.p[0][0][cc] + u.s.p[1][0][cc] + u.s.p[2][0][cc] + u.s.p[3][0][cc] + bias;
                    y1 = u.s.p[0][1][cc] + u.s.p[1][1][cc] + u.s.p[2][1][cc] + u.s.p[3][1][cc] + bias;
                }
                float s0 = y0, s1 = y1, q0 = y0 * y0, q1 = y1 * y1;
                bsum4_512(s0, s1, q0, q1, u.s.red);
                if (act) {
                    float mu0 = s0 * (1.0f / H2), mu1 = s1 * (1.0f / H2);
                    float v0 = q0 * (1.0f / H2) - mu0 * mu0;
                    float v1 = q1 * (1.0f / H2) - mu1 * mu1;
                    float g = u.s.cg2[cc], bb = u.s.cbt2[cc];
                    float h0 = gelu_exact((y0 - mu0) * rsqrtf(v0 + 1e-5f) * g + bb);
                    float h1 = gelu_exact((y1 - mu1) * rsqrtf(v1 + 1e-5f) * g + bb);
                    u.s.h2pair[cc] = pack2(h0, h1);
                }
            }
            __syncthreads();

            // ---- drift partials: smem fp16 M, packed f32x2 FMA ----
            {
                const __half2* mp = sM + (size_t)(jq * 64) * HID + c;
                const u64* hp = &u.s.h2pair[jq * 64];
                u64 acc = 0;
#pragma unroll 16
                for (int jj = 0; jj < 64; jj++) {
                    float2 mf = __half22float2(mp[(size_t)jj * HID]);
                    acc = fma2(pack2(mf.x, mf.y), hp[jj], acc);
                }
                u.s.dp2[jq][c] = acc;
            }
            __syncthreads();

            // ---- packed RK4 bookkeeping ----
            if (tid < HID) {
                int h = tid;
                u64 k  = add2(add2(add2(u.s.dp2[0][h], u.s.dp2[1][h]),
                                   add2(u.s.dp2[2][h], u.s.dp2[3][h])), u.s.b3e2[h]);
                u64 zc = u.s.zc2[h];
                u64 ka = u.s.ka2[h];
                u64 za = 0;
                if (st == 0)      { ka = k;                 za = fma2(hs_half, k, zc); }
                else if (st == 1) { ka = fma2(two2, k, ka); za = fma2(hs_half, k, zc); }
                else if (st == 2) { ka = fma2(two2, k, ka); za = fma2(hs_full, k, zc); }
                else {
                    ka = add2(ka, k);
                    u.s.zc2[h] = fma2(hs_six, ka, zc);
                }
                u.s.ka2[h] = ka;
                if (st < 3) {
                    float2 z = unpack2(za);
                    u.s.zrep[0][h] = pack2(z.x, z.x);
                    u.s.zrep[1][h] = pack2(z.y, z.y);
                }
            }
            __syncthreads();
        }

        // release ring slot l
        if (tid == 0) red_release(&sDone[l]);
    }

    // ---- head + decoder (softmax over size-1 axis == identity) ----
    if (tid < HID) {
        float2 z = unpack2(u.s.zc2[tid]);
        u.s.p[3][0][tid] = z.x;
        u.s.p[3][1][tid] = z.y;
    }
    __syncthreads();
    {
        int bl = tid >> 7, t = tid & 127;
        if (tid < 256) {
            float a = bv[t];
#pragma unroll 8
            for (int j = 0; j < HID; j++) a = fmaf(u.s.p[3][bl][j], Wv[j * HID + t], a);
            u.s.p[2][bl][t] = a;                // vs
        }
        __syncthreads();
        if (tid < 256) {
            float a = bo[t];
#pragma unroll 8
            for (int j = 0; j < HID; j++) a = fmaf(u.s.p[2][bl][j], Wo[j * HID + t], a);
            u.s.p[0][bl][t] = a;                // final
        }
        __syncthreads();
        if (tid < 256) {
            float a = db1[t];
#pragma unroll 8
            for (int j = 0; j < HID; j++) a = fmaf(u.s.p[0][bl][j], dW1[j * HID + t], a);
            u.s.p[1][bl][t] = gelu_exact(a);    // hD
        }
        __syncthreads();
        if (tid < 256 && t < 10) {
            float s = db2[t];
#pragma unroll 8
            for (int j = 0; j < HID; j++) s = fmaf(u.s.p[1][bl][j], dW2[j * 10 + t], s);
            int idx = (b0 + bl) * 10 + t;
            if (idx < out_size) out[idx] = s;
        }
        if (tid < 2) {
            int aidx = BATCH * 10 + b0 + tid;
            if (aidx < out_size) out[aidx] = 1.0f;
        }
    }
}

// ---------------- launch: single stream, 2 graph nodes --------------------
extern "C" void kernel_launch(void* const* d_in, const int* in_sizes, int n_in,
                              void* d_out, int out_size)
{
    const float* path = (const float*)d_in[0];
    const float* ts   = (const float*)d_in[1];
    const float* eW1  = (const float*)d_in[2];
    const float* eb1  = (const float*)d_in[3];
    const float* eg1  = (const float*)d_in[4];
    const float* ebt1 = (const float*)d_in[5];
    const float* eW2  = (const float*)d_in[6];
    const float* eb2  = (const float*)d_in[7];
    const float* eg2  = (const float*)d_in[8];
    const float* ebt2 = (const float*)d_in[9];
    const float* vW1  = (const float*)d_in[10];
    const float* vb1  = (const float*)d_in[11];
    const float* vg1  = (const float*)d_in[12];
    const float* vbt1 = (const float*)d_in[13];
    const float* vW2  = (const float*)d_in[14];
    const float* vb2  = (const float*)d_in[15];
    const float* vg2  = (const float*)d_in[16];
    const float* vbt2 = (const float*)d_in[17];
    const float* vW3  = (const float*)d_in[18];
    const float* vb3  = (const float*)d_in[19];
    // d_in[20..23] = Wq,bq,Wk,bk  (mathematically unused: softmax over size-1 axis)
    const float* Wv   = (const float*)d_in[24];
    const float* bv   = (const float*)d_in[25];
    const float* Wo   = (const float*)d_in[26];
    const float* bo   = (const float*)d_in[27];
    const float* dW1  = (const float*)d_in[28];
    const float* db1  = (const float*)d_in[29];
    const float* dW2  = (const float*)d_in[30];
    const float* db2  = (const float*)d_in[31];

    cudaFuncSetAttribute(fused_all, cudaFuncAttributeMaxDynamicSharedMemorySize, DYN_SMEM);

    init_kernel<<<BATCH, HID>>>(path, ts, eW1, eb1, eg1, ebt1, eW2, eb2, eg2, ebt2);

    fused_all<<<NSB + NGB, NTHR, DYN_SMEM>>>(vW3,
                                   vW1, vb1, vg1, vbt1,
                                   vW2, vb2, vg2, vbt2, vb3,
                                   Wv, bv, Wo, bo, dW1, db1, dW2, db2,
                                   (float*)d_out, out_size);
}

// round 17
// speedup vs baseline: 2.5434x; 1.0268x over previous
#include <cuda_runtime.h>
#include <cuda_fp16.h>
#include <math.h>

#define BATCH 128
#define SEQ   32
#define IND   32
#define HID   128
#define H2    256      // 2*HID
#define NSTEP 31
#define NBP   64       // batch pairs
#define NBUF  6        // M ring depth (6 x 8MB fp16 ~ 50MB, L2-resident)
#define NSB   64       // S blocks (batch pairs)
#define NGB   64       // G blocks (4 j-rows each)
#define NTHR  512
#define DYN_SMEM (H2 * HID * 4)   // 131072 B: fp16 M tile [H2][HID] of half2

typedef unsigned long long u64;

// ---------------- device scratch (static, no allocation) ----------------
// M ring, fp16, packed by batch-pair: gMh[l%NBUF][bp][j][h] = (M_b0, M_b1)
__device__ __half2 gMh[NBUF][NBP][H2][HID];
__device__ float gZ[BATCH][HID];
__device__ float gDX[NSTEP][BATCH][IND];
__device__ float gDts[NSTEP][BATCH];
__device__ int   gDone[NSTEP];   // G blocks finished step l
__device__ int   sDone[NSTEP];   // S blocks finished consuming step l

// ---------------- helpers ------------------------------------------------
__device__ __forceinline__ u64 fma2(u64 a, u64 b, u64 c) {
    u64 d; asm("fma.rn.f32x2 %0, %1, %2, %3;" : "=l"(d) : "l"(a), "l"(b), "l"(c)); return d;
}
__device__ __forceinline__ u64 add2(u64 a, u64 b) {
    u64 d; asm("add.rn.f32x2 %0, %1, %2;" : "=l"(d) : "l"(a), "l"(b)); return d;
}
__device__ __forceinline__ u64 pack2(float x, float y) {
    u64 r; asm("mov.b64 %0, {%1, %2};" : "=l"(r) : "f"(x), "f"(y)); return r;
}
__device__ __forceinline__ float2 unpack2(u64 v) {
    float2 r; asm("mov.b64 {%0, %1}, %2;" : "=f"(r.x), "=f"(r.y) : "l"(v)); return r;
}
__device__ __forceinline__ int ld_acq(const int* p) {
    int v; asm volatile("ld.acquire.gpu.global.b32 %0, [%1];" : "=r"(v) : "l"(p)); return v;
}
__device__ __forceinline__ void red_release(int* p) {
    asm volatile("red.release.gpu.global.add.s32 [%0], %1;" :: "l"(p), "r"(1) : "memory");
}
// L2-only (coherent) vector load for ring-buffer M copy
__device__ __forceinline__ uint4 ldcg4(const uint4* p) {
    uint4 v;
    asm volatile("ld.global.cg.v4.u32 {%0,%1,%2,%3}, [%4];"
                 : "=r"(v.x), "=r"(v.y), "=r"(v.z), "=r"(v.w) : "l"(p));
    return v;
}

__device__ __forceinline__ float gelu_exact(float x) {
    return 0.5f * x * (1.0f + erff(x * 0.70710678118654752440f));
}

// block-wide sum for 128 threads (4 warps)
__device__ __forceinline__ float bsum128(float v, float* red) {
#pragma unroll
    for (int o = 16; o > 0; o >>= 1) v += __shfl_xor_sync(0xffffffffu, v, o);
    __syncthreads();
    if ((threadIdx.x & 31) == 0) red[threadIdx.x >> 5] = v;
    __syncthreads();
    return red[0] + red[1] + red[2] + red[3];
}

// quad block-wide sum for 512 threads (16 warps), ONE barrier round
__device__ __forceinline__ void bsum4_512(float& a, float& b, float& c, float& d,
                                          float red[4][16]) {
#pragma unroll
    for (int o = 16; o > 0; o >>= 1) {
        a += __shfl_xor_sync(0xffffffffu, a, o);
        b += __shfl_xor_sync(0xffffffffu, b, o);
        c += __shfl_xor_sync(0xffffffffu, c, o);
        d += __shfl_xor_sync(0xffffffffu, d, o);
    }
    int w = threadIdx.x >> 5;
    if ((threadIdx.x & 31) == 0) { red[0][w] = a; red[1][w] = b; red[2][w] = c; red[3][w] = d; }
    __syncthreads();
    float A = 0.f, B = 0.f, C = 0.f, D = 0.f;
#pragma unroll
    for (int i = 0; i < 16; i++) { A += red[0][i]; B += red[1][i]; C += red[2][i]; D += red[3][i]; }
    a = A; b = B; c = C; d = D;
}

// ---------------- init: encoder -> z0, dts/dX, flag reset ----------------
__global__ __launch_bounds__(HID) void init_kernel(
    const float* __restrict__ path, const float* __restrict__ ts,
    const float* __restrict__ W1, const float* __restrict__ b1,
    const float* __restrict__ g1, const float* __restrict__ bt1,
    const float* __restrict__ W2, const float* __restrict__ b2,
    const float* __restrict__ g2, const float* __restrict__ bt2)
{
    int b = blockIdx.x;
    int t = threadIdx.x;  // 128 threads
    __shared__ float x0[IND];
    __shared__ float hb[HID];
    __shared__ float red[4];
    __shared__ float dtsh[NSTEP];

    if (b == 0 && t < NSTEP) { gDone[t] = 0; sDone[t] = 0; }   // reset flags every replay

    if (t < IND) x0[t] = path[(size_t)(b * SEQ) * IND + t];
    __syncthreads();

    float acc = b1[t];
#pragma unroll
    for (int i = 0; i < IND; i++) acc = fmaf(x0[i], W1[i * HID + t], acc);
    float mu  = bsum128(acc, red) * (1.0f / HID);
    float d   = acc - mu;
    float var = bsum128(d * d, red) * (1.0f / HID);
    float h0  = gelu_exact(d * rsqrtf(var + 1e-5f) * g1[t] + bt1[t]);
    hb[t] = h0;
    __syncthreads();

    float acc2 = b2[t];
#pragma unroll 8
    for (int j = 0; j < HID; j++) acc2 = fmaf(hb[j], W2[j * HID + t], acc2);
    mu  = bsum128(acc2, red) * (1.0f / HID);
    d   = acc2 - mu;
    var = bsum128(d * d, red) * (1.0f / HID);
    gZ[b][t] = d * rsqrtf(var + 1e-5f) * g2[t] + bt2[t];

    if (t < NSTEP) {
        float dt = ts[b * SEQ + t + 1] - ts[b * SEQ + t];
        dtsh[t] = dt;
        gDts[t][b] = dt;
    }
    __syncthreads();
    for (int idx = t; idx < NSTEP * IND; idx += HID) {
        int tt = idx >> 5, i = idx & 31;
        gDX[tt][b][i] = (path[(size_t)(b * SEQ + tt + 1) * IND + i] -
                         path[(size_t)(b * SEQ + tt) * IND + i]) / dtsh[tt];
    }
}

// ---------------- fused persistent kernel: 64 S blocks + 64 G blocks -----
// grid = 128 <= 148 SMs: every block is wave-1 resident => flag sync is safe.
struct __align__(16) SmemG { float2 dxp[NBP][IND]; };            // 16 KB
struct __align__(16) SmemS {
    alignas(16) u64   zrep2[HID][2];   // interleaved (b0rep, b1rep)   2 KB
    alignas(16) u64   h1rep2[H2][2];   //                              4 KB
    u64   h2pair[H2];        // (h2_b0, h2_b1)                   2 KB
    float p[4][2][H2];       // layer partials + head scratch    8 KB
    u64   dp2[4][HID];       // drift partials                   4 KB
    u64   zc2[HID], ka2[HID], b3e2[HID];                       // 3 KB
    float red[4][16];
    float dxs[2][IND];
    float hsm[2];
    float cb1[H2], cg1[H2], cbt1[H2], cb2[H2], cg2[H2], cbt2[H2]; // 6 KB
};
union __align__(16) FusedSmem { SmemG g; SmemS s; };

__global__ __launch_bounds__(NTHR, 1) void fused_all(
    const float* __restrict__ W3,
    const float* __restrict__ vW1, const float* __restrict__ vb1,
    const float* __restrict__ vg1, const float* __restrict__ vbt1,
    const float* __restrict__ vW2, const float* __restrict__ vb2,
    const float* __restrict__ vg2, const float* __restrict__ vbt2,
    const float* __restrict__ vb3,
    const float* __restrict__ Wv, const float* __restrict__ bv,
    const float* __restrict__ Wo, const float* __restrict__ bo,
    const float* __restrict__ dW1, const float* __restrict__ db1,
    const float* __restrict__ dW2, const float* __restrict__ db2,
    float* __restrict__ out, int out_size)
{
    extern __shared__ __align__(16) unsigned char dynsm[];
    __half2* sM = reinterpret_cast<__half2*>(dynsm);   // [H2][HID] M tile (S only)
    __shared__ FusedSmem u;
    int tid = threadIdx.x;

    if (blockIdx.x >= NSB) {
        // ================= G: M producer, 4 j-rows per block ==============
        int gb   = blockIdx.x - NSB;     // 0..63
        int jsub = tid >> 7, h = tid & 127;
        int j = gb * 4 + jsub;

        // W3 coefficients for (j,h), replicated, register-resident for all steps
        u64 wp[32];
        {
            const float4* wr = reinterpret_cast<const float4*>(W3 + (size_t)j * (HID * IND) + h * IND);
#pragma unroll
            for (int q = 0; q < 8; q++) {
                float4 w = wr[q];
                wp[4 * q + 0] = pack2(w.x, w.x);
                wp[4 * q + 1] = pack2(w.y, w.y);
                wp[4 * q + 2] = pack2(w.z, w.z);
                wp[4 * q + 3] = pack2(w.w, w.w);
            }
        }

        for (int l = 0; l < NSTEP; l++) {
            // ring backpressure: don't overwrite a slot S hasn't drained
            if (tid == 0 && l >= NBUF) {
                while (ld_acq(&sDone[l - NBUF]) < NSB) __nanosleep(128);
            }
            __syncthreads();

            const float* dxg = &gDX[l][0][0];
            for (int idx = tid; idx < NBP * IND; idx += NTHR) {
                int bp = idx >> 5, i = idx & 31;
                u.g.dxp[bp][i] = make_float2(dxg[(2 * bp) * IND + i],
                                             dxg[(2 * bp + 1) * IND + i]);
            }
            __syncthreads();

            __half2* outp = &gMh[l % NBUF][0][j][h];
#pragma unroll 2
            for (int bp = 0; bp < NBP; bp++) {
                const longlong2* dp = reinterpret_cast<const longlong2*>(u.g.dxp[bp]);
                u64 a0 = 0, a1 = 0, a2 = 0, a3 = 0;
#pragma unroll
                for (int q = 0; q < 16; q++) {
                    longlong2 v = dp[q];
                    if ((q & 1) == 0) {
                        a0 = fma2(wp[2 * q],     (u64)v.x, a0);
                        a1 = fma2(wp[2 * q + 1], (u64)v.y, a1);
                    } else {
                        a2 = fma2(wp[2 * q],     (u64)v.x, a2);
                        a3 = fma2(wp[2 * q + 1], (u64)v.y, a3);
                    }
                }
                float2 f = unpack2(add2(add2(a0, a1), add2(a2, a3)));
                outp[(size_t)bp * (H2 * HID)] = __floats2half2_rn(f.x, f.y);
            }

            // one-thread release after barrier (replaces 256 MEMBARs)
            __syncthreads();
            if (tid == 0) red_release(&gDone[l]);
        }
        return;
    }

    // ================= S: persistent RK4 scan + head/decoder =============
    int bp = blockIdx.x;
    int b0 = bp * 2;
    int jq = tid >> 7, c = tid & 127;

    if (tid < H2) {
        u.s.cb1[tid] = vb1[tid]; u.s.cg1[tid] = vg1[tid]; u.s.cbt1[tid] = vbt1[tid];
        u.s.cb2[tid] = vb2[tid]; u.s.cg2[tid] = vg2[tid]; u.s.cbt2[tid] = vbt2[tid];
    } else if (tid < H2 + HID) {
        int h = tid - H2;
        u.s.zc2[h] = pack2(gZ[b0][h], gZ[b0 + 1][h]);
    }
    __syncthreads();

    for (int l = 0; l < NSTEP; l++) {
        if (tid == 0) {
            while (ld_acq(&gDone[l]) < NGB) __nanosleep(64);
        }
        __syncthreads();

        // ---- stage M tile into smem: 128 KB coherent .cg copy ----
        {
            const uint4* src = reinterpret_cast<const uint4*>(&gMh[l % NBUF][bp][0][0]);
            uint4* dst = reinterpret_cast<uint4*>(sM);
#pragma unroll
            for (int it = 0; it < 16; it++) {
                int idx = it * NTHR + tid;
                dst[idx] = ldcg4(src + idx);
            }
        }
        if (tid < 64) { int b = tid >> 5, i = tid & 31; u.s.dxs[b][i] = gDX[l][b0 + b][i]; }
        if (tid < 2)  u.s.hsm[tid] = gDts[l][b0 + tid];
        __syncthreads();

        if (tid < HID) {
            float a0 = 0.f, a1 = 0.f;
            const float* w = vb3 + tid * IND;
#pragma unroll
            for (int i = 0; i < IND; i++) {
                a0 = fmaf(w[i], u.s.dxs[0][i], a0);
                a1 = fmaf(w[i], u.s.dxs[1][i], a1);
            }
            u.s.b3e2[tid] = pack2(a0, a1);
            float2 z = unpack2(u.s.zc2[tid]);
            ulonglong2 zz; zz.x = pack2(z.x, z.x); zz.y = pack2(z.y, z.y);
            *reinterpret_cast<ulonglong2*>(&u.s.zrep2[tid][0]) = zz;
            u.s.ka2[tid] = 0ull;
        }
        __syncthreads();

        float hsA = u.s.hsm[0], hsB = u.s.hsm[1];
        u64 hs_half = pack2(0.5f * hsA, 0.5f * hsB);
        u64 hs_full = pack2(hsA, hsB);
        u64 hs_six  = pack2(hsA * (1.0f / 6.0f), hsB * (1.0f / 6.0f));
        u64 two2    = pack2(2.0f, 2.0f);

#pragma unroll 1
        for (int st = 0; st < 4; st++) {
            // ---- vf layer 1 partials: 16-deep prefetch, LDS.128 activations ----
            {
                const u64* w = reinterpret_cast<const u64*>(vW1) + (size_t)(jq * 32) * (H2 / 2) + c;
                const ulonglong2* zp = reinterpret_cast<const ulonglong2*>(u.s.zrep2) + jq * 32;
                u64 a0 = 0, a1 = 0;
#pragma unroll
                for (int ph = 0; ph < 2; ph++) {
                    u64 wbuf[16];
#pragma unroll
                    for (int q = 0; q < 16; q++)
                        wbuf[q] = w[(size_t)(ph * 16 + q) * (H2 / 2)];
#pragma unroll
                    for (int q = 0; q < 16; q++) {
                        ulonglong2 zv = zp[ph * 16 + q];
                        a0 = fma2(wbuf[q], zv.x, a0);
                        a1 = fma2(wbuf[q], zv.y, a1);
                    }
                }
                *reinterpret_cast<float2*>(&u.s.p[jq][0][2 * c]) = unpack2(a0);
                *reinterpret_cast<float2*>(&u.s.p[jq][1][2 * c]) = unpack2(a1);
            }
            __syncthreads();

            // ---- LN1 + gelu ----
            {
                float y0 = 0.f, y1 = 0.f;
                bool act = tid < H2;
                int cc = tid & (H2 - 1);
                if (act) {
                    float bias = u.s.cb1[cc];
                    y0 = u.s.p[0][0][cc] + u.s.p[1][0][cc] + u.s.p[2][0][cc] + u.s.p[3][0][cc] + bias;
                    y1 = u.s.p[0][1][cc] + u.s.p[1][1][cc] + u.s.p[2][1][cc] + u.s.p[3][1][cc] + bias;
                }
                float s0 = y0, s1 = y1, q0 = y0 * y0, q1 = y1 * y1;
                bsum4_512(s0, s1, q0, q1, u.s.red);
                if (act) {
                    float mu0 = s0 * (1.0f / H2), mu1 = s1 * (1.0f / H2);
                    float v0 = q0 * (1.0f / H2) - mu0 * mu0;
                    float v1 = q1 * (1.0f / H2) - mu1 * mu1;
                    float g = u.s.cg1[cc], bb = u.s.cbt1[cc];
                    float h0 = gelu_exact((y0 - mu0) * rsqrtf(v0 + 1e-5f) * g + bb);
                    float h1 = gelu_exact((y1 - mu1) * rsqrtf(v1 + 1e-5f) * g + bb);
                    ulonglong2 hh; hh.x = pack2(h0, h0); hh.y = pack2(h1, h1);
                    *reinterpret_cast<ulonglong2*>(&u.s.h1rep2[cc][0]) = hh;
                }
            }
            __syncthreads();

            // ---- vf layer 2 partials: 16-deep prefetch x4 phases ----
            {
                const u64* w = reinterpret_cast<const u64*>(vW2) + (size_t)(jq * 64) * (H2 / 2) + c;
                const ulonglong2* hp = reinterpret_cast<const ulonglong2*>(u.s.h1rep2) + jq * 64;
                u64 a0 = 0, a1 = 0;
#pragma unroll
                for (int ph = 0; ph < 4; ph++) {
                    u64 wbuf[16];
#pragma unroll
                    for (int q = 0; q < 16; q++)
                        wbuf[q] = w[(size_t)(ph * 16 + q) * (H2 / 2)];
#pragma unroll
                    for (int q = 0; q < 16; q++) {
                        ulonglong2 hv = hp[ph * 16 + q];
                        a0 = fma2(wbuf[q], hv.x, a0);
                        a1 = fma2(wbuf[q], hv.y, a1);
                    }
                }
                *reinterpret_cast<float2*>(&u.s.p[jq][0][2 * c]) = unpack2(a0);
                *reinterpret_cast<float2*>(&u.s.p[jq][1][2 * c]) = unpack2(a1);
            }
            __syncthreads();

            // ---- LN2 + gelu -> h2pair (lanes = batches) ----
            {
                float y0 = 0.f, y1 = 0.f;
                bool act = tid < H2;
                int cc = tid & (H2 - 1);
                if (act) {
                    float bias = u.s.cb2[cc];
                    y0 = u.s.p[0][0][cc] + u.s.p[1][0][cc] + u.s.p[2][0][cc] + u.s.p[3][0][cc] + bias;
                    y1 = u.s.p[0][1][cc] + u.s.p[1][1][cc] + u.s.p[2][1][cc] + u.s.p[3][1][cc] + bias;
                }
                float s0 = y0, s1 = y1, q0 = y0 * y0, q1 = y1 * y1;
                bsum4_512(s0, s1, q0, q1, u.s.red);
                if (act) {
                    float mu0 = s0 * (1.0f / H2), mu1 = s1 * (1.0f / H2);
                    float v0 = q0 * (1.0f / H2) - mu0 * mu0;
                    float v1 = q1 * (1.0f / H2) - mu1 * mu1;
                    float g = u.s.cg2[cc], bb = u.s.cbt2[cc];
                    float h0 = gelu_exact((y0 - mu0) * rsqrtf(v0 + 1e-5f) * g + bb);
                    float h1 = gelu_exact((y1 - mu1) * rsqrtf(v1 + 1e-5f) * g + bb);
                    u.s.h2pair[cc] = pack2(h0, h1);
                }
            }
            __syncthreads();

            // ---- drift partials: smem fp16 M, packed f32x2 FMA ----
            {
                const __half2* mp = sM + (size_t)(jq * 64) * HID + c;
                const u64* hp = &u.s.h2pair[jq * 64];
                u64 acc = 0;
#pragma unroll 16
                for (int jj = 0; jj < 64; jj++) {
                    float2 mf = __half22float2(mp[(size_t)jj * HID]);
                    acc = fma2(pack2(mf.x, mf.y), hp[jj], acc);
                }
                u.s.dp2[jq][c] = acc;
            }
            __syncthreads();

            // ---- packed RK4 bookkeeping ----
            if (tid < HID) {
                int h = tid;
                u64 k  = add2(add2(add2(u.s.dp2[0][h], u.s.dp2[1][h]),
                                   add2(u.s.dp2[2][h], u.s.dp2[3][h])), u.s.b3e2[h]);
                u64 zc = u.s.zc2[h];
                u64 ka = u.s.ka2[h];
                u64 za = 0;
                if (st == 0)      { ka = k;                 za = fma2(hs_half, k, zc); }
                else if (st == 1) { ka = fma2(two2, k, ka); za = fma2(hs_half, k, zc); }
                else if (st == 2) { ka = fma2(two2, k, ka); za = fma2(hs_full, k, zc); }
                else {
                    ka = add2(ka, k);
                    u.s.zc2[h] = fma2(hs_six, ka, zc);
                }
                u.s.ka2[h] = ka;
                if (st < 3) {
                    float2 z = unpack2(za);
                    ulonglong2 zz; zz.x = pack2(z.x, z.x); zz.y = pack2(z.y, z.y);
                    *reinterpret_cast<ulonglong2*>(&u.s.zrep2[h][0]) = zz;
                }
            }
            __syncthreads();
        }

        // release ring slot l
        if (tid == 0) red_release(&sDone[l]);
    }

    // ---- head + decoder (softmax over size-1 axis == identity) ----
    if (tid < HID) {
        float2 z = unpack2(u.s.zc2[tid]);
        u.s.p[3][0][tid] = z.x;
        u.s.p[3][1][tid] = z.y;
    }
    __syncthreads();
    {
        int bl = tid >> 7, t = tid & 127;
        if (tid < 256) {
            float a = bv[t];
#pragma unroll 8
            for (int j = 0; j < HID; j++) a = fmaf(u.s.p[3][bl][j], Wv[j * HID + t], a);
            u.s.p[2][bl][t] = a;                // vs
        }
        __syncthreads();
        if (tid < 256) {
            float a = bo[t];
#pragma unroll 8
            for (int j = 0; j < HID; j++) a = fmaf(u.s.p[2][bl][j], Wo[j * HID + t], a);
            u.s.p[0][bl][t] = a;                // final
        }
        __syncthreads();
        if (tid < 256) {
            float a = db1[t];
#pragma unroll 8
            for (int j = 0; j < HID; j++) a = fmaf(u.s.p[0][bl][j], dW1[j * HID + t], a);
            u.s.p[1][bl][t] = gelu_exact(a);    // hD
        }
        __syncthreads();
        if (tid < 256 && t < 10) {
            float s = db2[t];
#pragma unroll 8
            for (int j = 0; j < HID; j++) s = fmaf(u.s.p[1][bl][j], dW2[j * 10 + t], s);
            int idx = (b0 + bl) * 10 + t;
            if (idx < out_size) out[idx] = s;
        }
        if (tid < 2) {
            int aidx = BATCH * 10 + b0 + tid;
            if (aidx < out_size) out[aidx] = 1.0f;
        }
    }
}

// ---------------- launch: single stream, 2 graph nodes --------------------
extern "C" void kernel_launch(void* const* d_in, const int* in_sizes, int n_in,
                              void* d_out, int out_size)
{
    const float* path = (const float*)d_in[0];
    const float* ts   = (const float*)d_in[1];
    const float* eW1  = (const float*)d_in[2];
    const float* eb1  = (const float*)d_in[3];
    const float* eg1  = (const float*)d_in[4];
    const float* ebt1 = (const float*)d_in[5];
    const float* eW2  = (const float*)d_in[6];
    const float* eb2  = (const float*)d_in[7];
    const float* eg2  = (const float*)d_in[8];
    const float* ebt2 = (const float*)d_in[9];
    const float* vW1  = (const float*)d_in[10];
    const float* vb1  = (const float*)d_in[11];
    const float* vg1  = (const float*)d_in[12];
    const float* vbt1 = (const float*)d_in[13];
    const float* vW2  = (const float*)d_in[14];
    const float* vb2  = (const float*)d_in[15];
    const float* vg2  = (const float*)d_in[16];
    const float* vbt2 = (const float*)d_in[17];
    const float* vW3  = (const float*)d_in[18];
    const float* vb3  = (const float*)d_in[19];
    // d_in[20..23] = Wq,bq,Wk,bk  (mathematically unused: softmax over size-1 axis)
    const float* Wv   = (const float*)d_in[24];
    const float* bv   = (const float*)d_in[25];
    const float* Wo   = (const float*)d_in[26];
    const float* bo   = (const float*)d_in[27];
    const float* dW1  = (const float*)d_in[28];
    const float* db1  = (const float*)d_in[29];
    const float* dW2  = (const float*)d_in[30];
    const float* db2  = (const float*)d_in[31];

    cudaFuncSetAttribute(fused_all, cudaFuncAttributeMaxDynamicSharedMemorySize, DYN_SMEM);

    init_kernel<<<BATCH, HID>>>(path, ts, eW1, eb1, eg1, ebt1, eW2, eb2, eg2, ebt2);

    fused_all<<<NSB + NGB, NTHR, DYN_SMEM>>>(vW3,
                                   vW1, vb1, vg1, vbt1,
                                   vW2, vb2, vg2, vbt2, vb3,
                                   Wv, bv, Wo, bo, dW1, db1, dW2, db2,
                                   (float*)d_out, out_size);
}